// round 4
// baseline (speedup 1.0000x reference)
#include <cuda_runtime.h>
#include <math.h>

#define BN    32
#define NODES 202
#define NI    200
#define DD    64
#define JT    8
#define NTILES (NI/JT)   // 25
#define EPS   1e-5f
#define SLOPE 0.01f

typedef unsigned long long u64;

// ---- packed fp32x2 helpers (sm_103a) ----
__device__ __forceinline__ u64 f2_mul(u64 a, u64 b) {
    u64 r; asm("mul.rn.f32x2 %0,%1,%2;" : "=l"(r) : "l"(a), "l"(b)); return r;
}
__device__ __forceinline__ u64 f2_add(u64 a, u64 b) {
    u64 r; asm("add.rn.f32x2 %0,%1,%2;" : "=l"(r) : "l"(a), "l"(b)); return r;
}
__device__ __forceinline__ u64 f2_fma(u64 a, u64 b, u64 c) {
    u64 r; asm("fma.rn.f32x2 %0,%1,%2,%3;" : "=l"(r) : "l"(a), "l"(b), "l"(c)); return r;
}
__device__ __forceinline__ void f2_unpack(u64 v, float& lo, float& hi) {
    asm("mov.b64 {%0,%1},%2;" : "=f"(lo), "=f"(hi) : "l"(v));
}

// ---------------- device scratch ----------------
__device__ float g_ua[BN * NI * DD];
__device__ float g_prm[BN * NI * 8];     // (q1,k1,iZ1,q2),(k2,iZ2,_,_)

// =======================================================================
// kA: per-batch prep. grid (2, BN), 256 threads, dynamic smem.
#define A_W    0        // 2*64*64 = 8192   W_s[h*4096 + o*64 + d]
#define A_A    8192     // 2*192   = 384
#define A_WB   8576     // 2*64    = 128
#define A_UA   8704     // 200*68  = 13600
#define A_UID  22304    // 64
#define A_IID  22368    // 64
#define A_VQ   22432    // 2*64
#define A_VK   22560    // 2*64
#define A_SK   22688    // 2*200 = 400
#define A_RED  23088    // 8
#define A_CQK  23096    // 6 (cq,ck,ci per head)
#define A_QC   23102    // 2
#define A_KC   23104    // 2
#define A_FLOATS 23108
#define A_BYTES  (A_FLOATS * 4)

extern __shared__ float smA[];

__global__ __launch_bounds__(256, 1)
void kA_prep(const float* __restrict__ emb,
             const float* __restrict__ lnw, const float* __restrict__ lnb,
             const float* __restrict__ W1, const float* __restrict__ W1b,
             const float* __restrict__ W2, const float* __restrict__ W2b,
             const float* __restrict__ a1, const float* __restrict__ a1b,
             const float* __restrict__ a2, const float* __restrict__ a2b,
             float* __restrict__ out) {
    int half = blockIdx.x;
    int b    = blockIdx.y;
    int t    = threadIdx.x;
    int warp = t >> 5, lane = t & 31;

    float* W_s  = smA + A_W;
    float* a_s  = smA + A_A;
    float* wb_s = smA + A_WB;
    float* ua_s = smA + A_UA;   // stride 68
    float* uid  = smA + A_UID;
    float* iid  = smA + A_IID;
    float* vq_s = smA + A_VQ;
    float* vk_s = smA + A_VK;
    float* sk   = smA + A_SK;
    float* red  = smA + A_RED;
    float* cqk  = smA + A_CQK;
    float* qc_s = smA + A_QC;
    float* kc_s = smA + A_KC;

    // --- stage weights ---
    for (int idx = t; idx < 2048; idx += 256) {
        int h = idx >> 10;
        ((float4*)W_s)[idx] = ((const float4*)(h ? W2 : W1))[idx & 1023];
    }
    for (int idx = t; idx < 384; idx += 256)
        a_s[idx] = (idx < 192) ? a1[idx] : a2[idx - 192];
    if (t < 128) wb_s[t] = (t < 64) ? W1b[t] : W2b[t - 64];
    __syncthreads();

    // --- LN rows 0,1 (warps 0,1) ---
    if (warp < 2) {
        const float* x = emb + (size_t)(b * NODES + warp) * DD;
        float a = x[lane], c = x[lane + 32];
        float s = a + c;
        #pragma unroll
        for (int o = 16; o > 0; o >>= 1) s += __shfl_xor_sync(0xffffffffu, s, o);
        float mu = s * (1.f / DD);
        float da = a - mu, dc = c - mu;
        float q = fmaf(da, da, dc * dc);
        #pragma unroll
        for (int o = 16; o > 0; o >>= 1) q += __shfl_xor_sync(0xffffffffu, q, o);
        float rs = rsqrtf(q * (1.f / DD) + EPS);
        float* dst = warp == 0 ? uid : iid;
        dst[lane]      = fmaf(da * rs, lnw[lane],      lnb[lane]);
        dst[lane + 32] = fmaf(dc * rs, lnw[lane + 32], lnb[lane + 32]);
    }
    __syncthreads();

    // --- LN rows 2..201, multiplied by uid -> ua ---
    for (int r = warp; r < NI; r += 8) {
        const float* x = emb + (size_t)(b * NODES + 2 + r) * DD;
        float a = x[lane], c = x[lane + 32];
        float s = a + c;
        #pragma unroll
        for (int o = 16; o > 0; o >>= 1) s += __shfl_xor_sync(0xffffffffu, s, o);
        float mu = s * (1.f / DD);
        float da = a - mu, dc = c - mu;
        float q = fmaf(da, da, dc * dc);
        #pragma unroll
        for (int o = 16; o > 0; o >>= 1) q += __shfl_xor_sync(0xffffffffu, q, o);
        float rs = rsqrtf(q * (1.f / DD) + EPS);
        float u0 = fmaf(da * rs, lnw[lane],      lnb[lane])      * uid[lane];
        float u1 = fmaf(dc * rs, lnw[lane + 32], lnb[lane + 32]) * uid[lane + 32];
        ua_s[r * 68 + lane]      = u0;
        ua_s[r * 68 + lane + 32] = u1;
        if (r >= half * 100 && r < half * 100 + 100) {
            g_ua[((size_t)b * NI + r) * DD + lane]      = u0;
            g_ua[((size_t)b * NI + r) * DD + lane + 32] = u1;
        }
    }

    // --- fold: vq,vk,vi (t<128) ; bias dots cq/ck/ci (threads 240..245) ---
    if (t < 128) {
        int h = t >> 6, d = t & 63;
        const float* Wp = W_s + h * 4096 + d;
        const float* ap = a_s + h * 192;
        float sq = 0.f, sk2 = 0.f, si = 0.f;
        #pragma unroll 8
        for (int o = 0; o < DD; o++) {
            float wv = Wp[o * 64];
            sq  = fmaf(ap[o],       wv, sq);
            sk2 = fmaf(ap[64 + o],  wv, sk2);
            si  = fmaf(ap[128 + o], wv, si);
        }
        vq_s[h * 64 + d] = sq;
        vk_s[h * 64 + d] = sk2;
        float viid = si * iid[d];
        #pragma unroll
        for (int o = 16; o > 0; o >>= 1) viid += __shfl_xor_sync(0xffffffffu, viid, o);
        if (lane == 0) red[warp] = viid;
    }
    if (t >= 240 && t < 246) {
        int idx = t - 240;            // 0..5 : h*3 + which (0=q,1=k,2=i)
        int h = idx / 3, which = idx % 3;
        float s = 0.f;
        #pragma unroll 8
        for (int o = 0; o < DD; o++)
            s = fmaf(a_s[h * 192 + which * 64 + o], wb_s[h * 64 + o], s);
        cqk[idx] = s;
    }
    __syncthreads();
    if (t == 0) {
        qc_s[0] = red[0] + red[1] + cqk[0] + cqk[2] + a1b[0];  // iid.vi + cq + ci + ab
        kc_s[0] = cqk[1];
        qc_s[1] = red[2] + red[3] + cqk[3] + cqk[5] + a2b[0];
        kc_s[1] = cqk[4];
    }
    if (half == 0 && t < DD) {
        float u = uid[t] * iid[t];
        out[(size_t)(b * 201) * DD + t] = u > 0.f ? u : SLOPE * u;
    }
    __syncthreads();

    // --- q/k dots for all rows ---
    float q1 = 0.f, q2 = 0.f;
    if (t < NI) {
        const float* u = ua_s + t * 68;
        float s10 = 0, s20 = 0, s11 = 0, s21 = 0;
        #pragma unroll 8
        for (int d = 0; d < DD; d++) {
            float uv = u[d];
            s10 = fmaf(uv, vq_s[d],      s10);
            s20 = fmaf(uv, vk_s[d],      s20);
            s11 = fmaf(uv, vq_s[64 + d], s11);
            s21 = fmaf(uv, vk_s[64 + d], s21);
        }
        q1 = s10 + qc_s[0];
        q2 = s11 + qc_s[1];
        sk[t]       = s20 + kc_s[0];
        sk[200 + t] = s21 + kc_s[1];
    }
    __syncthreads();

    // --- softmax Z for own half ---
    if (t >= half * 100 && t < half * 100 + 100) {
        float Z1 = 0.f, Z2 = 0.f;
        #pragma unroll 4
        for (int j = 0; j < NI; j++) {
            float s = q1 + sk[j];       s = s > 0.f ? s : SLOPE * s; Z1 += __expf(s);
            float r = q2 + sk[200 + j]; r = r > 0.f ? r : SLOPE * r; Z2 += __expf(r);
        }
        float4* p = (float4*)(g_prm + (size_t)(b * NI + t) * 8);
        p[0] = make_float4(q1, sk[t], 1.f / Z1, q2);
        p[1] = make_float4(sk[200 + t], 1.f / Z2, 0.f, 0.f);
    }
}

// =======================================================================
// K3: main fused pair kernel
#define OFF_UA   0
#define OFF_KK1  13600
#define OFF_KK2  13800
#define OFF_C12  14000
#define OFF_WLN  18000
#define OFF_BLN  18064
#define OFF_SC   18128
#define OFF_RED  18160
#define SMEM_FLOATS (OFF_RED + 256)   // 18416
#define SMEM_BYTES  (SMEM_FLOATS * 4)

extern __shared__ float sm3[];

__global__ __launch_bounds__(256, 3)
void k3_main(const float* __restrict__ lnw, const float* __restrict__ lnb,
             float* __restrict__ out) {
    int jt = blockIdx.x;
    int b  = blockIdx.y;
    int t  = threadIdx.x;
    int warp = t >> 5, lane = t & 31;

    float* ua_s = sm3 + OFF_UA;     // stride 68
    float* kk1  = sm3 + OFF_KK1;
    float* kk2  = sm3 + OFF_KK2;
    float* c12  = sm3 + OFF_C12;    // stride 20: [i][jj*2+h]
    float* wln  = sm3 + OFF_WLN;
    float* bln  = sm3 + OFF_BLN;
    float* Sc   = sm3 + OFF_SC;
    float* red  = sm3 + OFF_RED;

    const float4* uab4 = (const float4*)(g_ua + (size_t)b * NI * DD);
    for (int idx = t; idx < NI * 16; idx += 256) {
        int i = idx >> 4, c = idx & 15;
        *(float4*)(ua_s + i * 68 + c * 4) = uab4[idx];
    }
    if (t < 64) { wln[t] = lnw[t]; bln[t] = lnb[t]; }

    float q1 = 0, iZ1 = 0, q2 = 0, iZ2 = 0;
    if (t < NI) {
        const float4* pp = (const float4*)(g_prm + (size_t)(b * NI + t) * 8);
        float4 p0 = pp[0], p1 = pp[1];
        q1 = p0.x; kk1[t] = p0.y; iZ1 = p0.z; q2 = p0.w;
        kk2[t] = p1.x; iZ2 = p1.y;
    }
    __syncthreads();

    int jbase = jt * JT;

    // ---- phase 1: Gram stats (packed f32x2, j-register-tiled) ----
    u64 s1p[JT], s2p[JT];
    #pragma unroll
    for (int jj = 0; jj < JT; jj++) { s1p[jj] = 0ull; s2p[jj] = 0ull; }

    if (t < NI) {
        const float* ui = ua_s + t * 68;
        const float* ujb = ua_s + jbase * 68;
        #pragma unroll 4
        for (int dc = 0; dc < 16; dc++) {
            ulonglong2 u = *(const ulonglong2*)(ui + dc * 4);
            #pragma unroll
            for (int jj = 0; jj < JT; jj++) {
                ulonglong2 v = *(const ulonglong2*)(ujb + jj * 68 + dc * 4);  // broadcast
                u64 p0 = f2_mul(u.x, v.x);
                u64 p1 = f2_mul(u.y, v.y);
                s1p[jj] = f2_add(s1p[jj], p0);
                s1p[jj] = f2_add(s1p[jj], p1);
                s2p[jj] = f2_fma(p0, p0, s2p[jj]);
                s2p[jj] = f2_fma(p1, p1, s2p[jj]);
            }
        }
    }

    float ra[JT], rb[JT], rc[JT], rd[JT];
    float cst[2 * JT];
    if (t < NI) {
        #pragma unroll
        for (int jj = 0; jj < JT; jj++) {
            float l1, h1, l2, h2;
            f2_unpack(s1p[jj], l1, h1);
            f2_unpack(s2p[jj], l2, h2);
            float mu  = (l1 + h1) * (1.f / DD);
            float var = fmaf(-mu, mu, (l2 + h2) * (1.f / DD));
            float rr  = rsqrtf(var + EPS);
            int j = jbase + jj;
            float s = q1 + kk1[j]; s = s > 0.f ? s : SLOPE * s;
            float a1 = __expf(s) * iZ1;
            float c1 = a1 * rr;
            s = q2 + kk2[j]; s = s > 0.f ? s : SLOPE * s;
            float a2 = __expf(s) * iZ2;
            float c2 = a2 * rr;
            cst[jj * 2 + 0] = c1; cst[jj * 2 + 1] = c2;
            ra[jj] = a1; rb[jj] = a2; rc[jj] = c1 * mu; rd[jj] = c2 * mu;
        }
        float* crow = c12 + t * 20;
        #pragma unroll
        for (int k = 0; k < 4; k++)
            *(float4*)(crow + k * 4) = make_float4(cst[k*4], cst[k*4+1], cst[k*4+2], cst[k*4+3]);
    } else {
        #pragma unroll
        for (int jj = 0; jj < JT; jj++) { ra[jj] = 0; rb[jj] = 0; rc[jj] = 0; rd[jj] = 0; }
    }

    #pragma unroll
    for (int jj = 0; jj < JT; jj++) {
        float v0 = ra[jj], v1 = rb[jj], v2 = rc[jj], v3 = rd[jj];
        #pragma unroll
        for (int o = 16; o > 0; o >>= 1) {
            v0 += __shfl_xor_sync(0xffffffffu, v0, o);
            v1 += __shfl_xor_sync(0xffffffffu, v1, o);
            v2 += __shfl_xor_sync(0xffffffffu, v2, o);
            v3 += __shfl_xor_sync(0xffffffffu, v3, o);
        }
        if (lane == 0) {
            red[warp * 32 + jj * 4 + 0] = v0;
            red[warp * 32 + jj * 4 + 1] = v1;
            red[warp * 32 + jj * 4 + 2] = v2;
            red[warp * 32 + jj * 4 + 3] = v3;
        }
    }
    __syncthreads();
    if (t < 32) {
        float s = 0.f;
        #pragma unroll
        for (int w = 0; w < 8; w++) s += red[w * 32 + t];
        Sc[t] = s;
    }
    __syncthreads();

    // ---- phase 2: warp w owns j = jbase+w; lanes own d = 2*lane, 2*lane+1 ----
    {
        int j = jbase + warp;
        float a10 = 0.f, a11 = 0.f, a20 = 0.f, a21 = 0.f;
        const float* up = ua_s + 2 * lane;
        const float* cp = c12 + warp * 2;
        #pragma unroll 4
        for (int i = 0; i < NI; i++) {
            float2 u = *(const float2*)(up + i * 68);
            float2 c = *(const float2*)(cp + i * 20);   // broadcast
            a10 = fmaf(c.x, u.x, a10);
            a11 = fmaf(c.x, u.y, a11);
            a20 = fmaf(c.y, u.x, a20);
            a21 = fmaf(c.y, u.y, a21);
        }
        float S0a = Sc[warp * 4 + 0], S0b = Sc[warp * 4 + 1];
        float S2a = Sc[warp * 4 + 2], S2b = Sc[warp * 4 + 3];
        float2 uj = *(const float2*)(ua_s + j * 68 + 2 * lane);
        float2 wl = *(const float2*)(wln + 2 * lane);
        float2 bl = *(const float2*)(bln + 2 * lane);
        float at1 = fmaf(wl.x, fmaf(uj.x, a10, -S2a), bl.x * S0a);
        float at2 = fmaf(wl.x, fmaf(uj.x, a20, -S2b), bl.x * S0b);
        float ox = 0.5f * (at1 + at2);
        at1 = fmaf(wl.y, fmaf(uj.y, a11, -S2a), bl.y * S0a);
        at2 = fmaf(wl.y, fmaf(uj.y, a21, -S2b), bl.y * S0b);
        float oy = 0.5f * (at1 + at2);
        ox = ox > 0.f ? ox : SLOPE * ox;
        oy = oy > 0.f ? oy : SLOPE * oy;
        *(float2*)(out + (size_t)(b * 201 + 1 + j) * DD + 2 * lane) = make_float2(ox, oy);
    }
}

// ---------------- launch ----------------
extern "C" void kernel_launch(void* const* d_in, const int* in_sizes, int n_in,
                              void* d_out, int out_size) {
    const float* emb = (const float*)d_in[0];
    const float* lnw = (const float*)d_in[1];
    const float* lnb = (const float*)d_in[2];
    const float* W1  = (const float*)d_in[3];
    const float* W1b = (const float*)d_in[4];
    const float* W2  = (const float*)d_in[5];
    const float* W2b = (const float*)d_in[6];
    const float* a1  = (const float*)d_in[7];
    const float* a1b = (const float*)d_in[8];
    const float* a2  = (const float*)d_in[9];
    const float* a2b = (const float*)d_in[10];
    float* out = (float*)d_out;
    (void)in_sizes; (void)n_in; (void)out_size;

    cudaFuncSetAttribute(kA_prep, cudaFuncAttributeMaxDynamicSharedMemorySize, A_BYTES);
    cudaFuncSetAttribute(k3_main, cudaFuncAttributeMaxDynamicSharedMemorySize, SMEM_BYTES);

    dim3 gA(2, BN);
    kA_prep<<<gA, 256, A_BYTES>>>(emb, lnw, lnb, W1, W1b, W2, W2b,
                                  a1, a1b, a2, a2b, out);
    dim3 g3(NTILES, BN);
    k3_main<<<g3, 256, SMEM_BYTES>>>(lnw, lnb, out);
}

// round 5
// speedup vs baseline: 1.2179x; 1.2179x over previous
#include <cuda_runtime.h>
#include <math.h>

#define BN    32
#define NODES 202
#define NI    200
#define DD    64
#define JT    8
#define NTILES (NI/JT)   // 25
#define EPS   1e-5f
#define SLOPE 0.01f

typedef unsigned long long u64;

// ---- packed fp32x2 helpers (sm_103a) ----
__device__ __forceinline__ u64 f2_mul(u64 a, u64 b) {
    u64 r; asm("mul.rn.f32x2 %0,%1,%2;" : "=l"(r) : "l"(a), "l"(b)); return r;
}
__device__ __forceinline__ u64 f2_add(u64 a, u64 b) {
    u64 r; asm("add.rn.f32x2 %0,%1,%2;" : "=l"(r) : "l"(a), "l"(b)); return r;
}
__device__ __forceinline__ u64 f2_fma(u64 a, u64 b, u64 c) {
    u64 r; asm("fma.rn.f32x2 %0,%1,%2,%3;" : "=l"(r) : "l"(a), "l"(b), "l"(c)); return r;
}
__device__ __forceinline__ u64 f2_pack(float lo, float hi) {
    u64 r; asm("mov.b64 %0,{%1,%2};" : "=l"(r) : "f"(lo), "f"(hi)); return r;
}
__device__ __forceinline__ void f2_unpack(u64 v, float& lo, float& hi) {
    asm("mov.b64 {%0,%1},%2;" : "=f"(lo), "=f"(hi) : "l"(v));
}

// ---------------- device scratch ----------------
__device__ float g_ua[BN * NI * DD];
__device__ float g_prm[BN * NI * 8];     // (q1,k1,iZ1,q2),(k2,iZ2,_,_)

// =======================================================================
// kA: per-batch prep. grid (2, BN), 256 threads.
#define A_W    0        // 8192  W_s[h*4096+o*64+d]
#define A_A    8192     // 384
#define A_WB   8576     // 128
#define A_LNW  8704     // 64
#define A_LNB  8768     // 64
#define A_RAW  8832     // 202*68 = 13736
#define A_UAK  22568    // 200*68 = 13600
#define A_MU   36168    // 202
#define A_RS   36370    // 202
#define A_UID  36572    // 64
#define A_IID  36636    // 64
#define A_VQ   36700    // 128
#define A_VK   36828    // 128
#define A_SKA  36956    // 400 (k1[200],k2[200])
#define A_SQ   37356    // 400 (q1[200],q2[200])
#define A_ZP   37756    // 400
#define A_RED  38156    // 8
#define A_CQK  38164    // 6
#define A_QC   38170    // 2
#define A_KC   38172    // 2
#define A_FLOATS 38174
#define A_BYTES  (A_FLOATS * 4)

extern __shared__ float smA[];

__global__ __launch_bounds__(256, 1)
void kA_prep(const float* __restrict__ emb,
             const float* __restrict__ lnw, const float* __restrict__ lnb,
             const float* __restrict__ W1, const float* __restrict__ W1b,
             const float* __restrict__ W2, const float* __restrict__ W2b,
             const float* __restrict__ a1, const float* __restrict__ a1b,
             const float* __restrict__ a2, const float* __restrict__ a2b,
             float* __restrict__ out) {
    int half = blockIdx.x;
    int b    = blockIdx.y;
    int t    = threadIdx.x;
    int warp = t >> 5, lane = t & 31;

    float* W_s   = smA + A_W;
    float* a_s   = smA + A_A;
    float* wb_s  = smA + A_WB;
    float* lnw_s = smA + A_LNW;
    float* lnb_s = smA + A_LNB;
    float* raw   = smA + A_RAW;   // stride 68
    float* ua_s  = smA + A_UAK;   // stride 68
    float* mu_s  = smA + A_MU;
    float* rs_s  = smA + A_RS;
    float* uid   = smA + A_UID;
    float* iid   = smA + A_IID;
    float* vq_s  = smA + A_VQ;
    float* vk_s  = smA + A_VK;
    float* sk    = smA + A_SKA;
    float* sq    = smA + A_SQ;
    float* zp    = smA + A_ZP;
    float* red   = smA + A_RED;
    float* cqk   = smA + A_CQK;
    float* qc_s  = smA + A_QC;
    float* kc_s  = smA + A_KC;

    // ---- P0: stage everything ----
    for (int idx = t; idx < 2048; idx += 256) {
        int h = idx >> 10;
        ((float4*)W_s)[idx] = ((const float4*)(h ? W2 : W1))[idx & 1023];
    }
    for (int idx = t; idx < 384; idx += 256)
        a_s[idx] = (idx < 192) ? a1[idx] : a2[idx - 192];
    if (t < 128) wb_s[t] = (t < 64) ? W1b[t] : W2b[t - 64];
    if (t < 64) { lnw_s[t] = lnw[t]; lnb_s[t] = lnb[t]; }
    const float4* e4 = (const float4*)(emb + (size_t)b * NODES * DD);
    for (int idx = t; idx < NODES * 16; idx += 256) {
        int r = idx >> 4, c = idx & 15;
        *(float4*)(raw + r * 68 + c * 4) = e4[idx];
    }
    __syncthreads();

    // ---- P1: per-row stats (thread-per-row) + bias dots ----
    if (t < NODES) {
        const float* rp = raw + t * 68;
        float s = 0.f, ss = 0.f;
        #pragma unroll
        for (int c = 0; c < 16; c++) {
            float4 v = *(const float4*)(rp + c * 4);
            s += (v.x + v.y) + (v.z + v.w);
            ss = fmaf(v.x, v.x, fmaf(v.y, v.y, fmaf(v.z, v.z, fmaf(v.w, v.w, ss))));
        }
        float m = s * (1.f / DD);
        float var = fmaf(-m, m, ss * (1.f / DD));
        mu_s[t] = m;
        rs_s[t] = rsqrtf(var + EPS);
    }
    if (t >= 208 && t < 214) {
        int idx = t - 208, h = idx / 3, wch = idx % 3;
        float s = 0.f;
        #pragma unroll 8
        for (int o = 0; o < DD; o++)
            s = fmaf(a_s[h * 192 + wch * 64 + o], wb_s[h * 64 + o], s);
        cqk[idx] = s;
    }
    __syncthreads();

    // ---- P2: uid / iid ----
    if (t < 128) {
        int rw = t >> 6, d = t & 63;
        float v = fmaf((raw[rw * 68 + d] - mu_s[rw]) * rs_s[rw], lnw_s[d], lnb_s[d]);
        (rw ? iid : uid)[d] = v;
    }
    __syncthreads();
    if (half == 0 && t < DD) {
        float u = uid[t] * iid[t];
        out[(size_t)(b * 201) * DD + t] = u > 0.f ? u : SLOPE * u;
    }

    // ---- P3: vectorized ua pass ----
    for (int idx = t; idx < NI * 16; idx += 256) {
        int r = idx >> 4, c = idx & 15;
        float4 v = *(const float4*)(raw + (r + 2) * 68 + c * 4);
        float m = mu_s[r + 2], sc = rs_s[r + 2];
        float4 w4 = *(const float4*)(lnw_s + c * 4);
        float4 b4 = *(const float4*)(lnb_s + c * 4);
        float4 u4 = *(const float4*)(uid + c * 4);
        float4 o4;
        o4.x = fmaf((v.x - m) * sc, w4.x, b4.x) * u4.x;
        o4.y = fmaf((v.y - m) * sc, w4.y, b4.y) * u4.y;
        o4.z = fmaf((v.z - m) * sc, w4.z, b4.z) * u4.z;
        o4.w = fmaf((v.w - m) * sc, w4.w, b4.w) * u4.w;
        *(float4*)(ua_s + r * 68 + c * 4) = o4;
        if (r >= half * 100 && r < half * 100 + 100)
            ((float4*)(g_ua + ((size_t)b * NI + r) * DD))[c] = o4;
    }
    __syncthreads();

    // ---- P4: fold vq/vk + vi.iid ----
    if (t < 128) {
        int h = t >> 6, d = t & 63;
        const float* Wp = W_s + h * 4096 + d;
        const float* ap = a_s + h * 192;
        float sqv = 0.f, skv = 0.f, siv = 0.f;
        #pragma unroll 8
        for (int o = 0; o < DD; o++) {
            float wv = Wp[o * 64];
            sqv = fmaf(ap[o],        wv, sqv);
            skv = fmaf(ap[64 + o],   wv, skv);
            siv = fmaf(ap[128 + o],  wv, siv);
        }
        vq_s[h * 64 + d] = sqv;
        vk_s[h * 64 + d] = skv;
        float viid = siv * iid[d];
        #pragma unroll
        for (int o = 16; o > 0; o >>= 1) viid += __shfl_xor_sync(0xffffffffu, viid, o);
        if (lane == 0) red[warp] = viid;
    }
    __syncthreads();
    if (t == 0) {
        qc_s[0] = red[0] + red[1] + cqk[0] + cqk[2] + a1b[0];
        kc_s[0] = cqk[1];
        qc_s[1] = red[2] + red[3] + cqk[3] + cqk[5] + a2b[0];
        kc_s[1] = cqk[4];
    }
    __syncthreads();

    // ---- P5: q/k dots ----
    if (t < NI) {
        const float* u = ua_s + t * 68;
        float s10 = 0, s20 = 0, s11 = 0, s21 = 0;
        #pragma unroll 8
        for (int d = 0; d < DD; d++) {
            float uv = u[d];
            s10 = fmaf(uv, vq_s[d],      s10);
            s20 = fmaf(uv, vk_s[d],      s20);
            s11 = fmaf(uv, vq_s[64 + d], s11);
            s21 = fmaf(uv, vk_s[64 + d], s21);
        }
        sq[t]       = s10 + qc_s[0];
        sq[200 + t] = s11 + qc_s[1];
        sk[t]       = s20 + kc_s[0];
        sk[200 + t] = s21 + kc_s[1];
    }
    __syncthreads();

    // ---- P6: Z partials (2 j-segments per i) ----
    if (t < 200) {
        int seg = t / 100, il = t % 100;
        int i = half * 100 + il;
        float q1 = sq[i], q2 = sq[200 + i];
        float Z1 = 0.f, Z2 = 0.f;
        int j0 = seg * 100;
        #pragma unroll 4
        for (int jj = 0; jj < 100; jj++) {
            int j = j0 + jj;
            float s = q1 + sk[j];       s = s > 0.f ? s : SLOPE * s; Z1 += __expf(s);
            float r = q2 + sk[200 + j]; r = r > 0.f ? r : SLOPE * r; Z2 += __expf(r);
        }
        zp[seg * 100 + il]       = Z1;
        zp[200 + seg * 100 + il] = Z2;
    }
    __syncthreads();
    if (t < 100) {
        int i = half * 100 + t;
        float Z1 = zp[t] + zp[100 + t];
        float Z2 = zp[200 + t] + zp[300 + t];
        float4* p = (float4*)(g_prm + (size_t)(b * NI + i) * 8);
        p[0] = make_float4(sq[i], sk[i], 1.f / Z1, sq[200 + i]);
        p[1] = make_float4(sk[200 + i], 1.f / Z2, 0.f, 0.f);
    }
}

// =======================================================================
// K3: main fused pair kernel
#define OFF_UA   0
#define OFF_KK1  13600
#define OFF_KK2  13800
#define OFF_C12  14000
#define OFF_WLN  18000
#define OFF_BLN  18064
#define OFF_SC   18128
#define OFF_RED  18160
#define SMEM_FLOATS (OFF_RED + 256)   // 18416
#define SMEM_BYTES  (SMEM_FLOATS * 4)

extern __shared__ float sm3[];

__global__ __launch_bounds__(256, 3)
void k3_main(const float* __restrict__ lnw, const float* __restrict__ lnb,
             float* __restrict__ out) {
    int jt = blockIdx.x;
    int b  = blockIdx.y;
    int t  = threadIdx.x;
    int warp = t >> 5, lane = t & 31;

    float* ua_s = sm3 + OFF_UA;     // stride 68
    float* kk1  = sm3 + OFF_KK1;
    float* kk2  = sm3 + OFF_KK2;
    float* c12  = sm3 + OFF_C12;    // stride 20: [i][jj*2+h]
    float* wln  = sm3 + OFF_WLN;
    float* bln  = sm3 + OFF_BLN;
    float* Sc   = sm3 + OFF_SC;
    float* red  = sm3 + OFF_RED;

    const float4* uab4 = (const float4*)(g_ua + (size_t)b * NI * DD);
    for (int idx = t; idx < NI * 16; idx += 256) {
        int i = idx >> 4, c = idx & 15;
        *(float4*)(ua_s + i * 68 + c * 4) = uab4[idx];
    }
    if (t < 64) { wln[t] = lnw[t]; bln[t] = lnb[t]; }

    float q1 = 0, iZ1 = 0, q2 = 0, iZ2 = 0;
    if (t < NI) {
        const float4* pp = (const float4*)(g_prm + (size_t)(b * NI + t) * 8);
        float4 p0 = pp[0], p1 = pp[1];
        q1 = p0.x; kk1[t] = p0.y; iZ1 = p0.z; q2 = p0.w;
        kk2[t] = p1.x; iZ2 = p1.y;
    }
    __syncthreads();

    int jbase = jt * JT;

    // ---- phase 1: Gram stats (packed f32x2, j-register-tiled) ----
    u64 s1p[JT], s2p[JT];
    #pragma unroll
    for (int jj = 0; jj < JT; jj++) { s1p[jj] = 0ull; s2p[jj] = 0ull; }

    if (t < NI) {
        const float* ui = ua_s + t * 68;
        const float* ujb = ua_s + jbase * 68;
        #pragma unroll 4
        for (int dc = 0; dc < 16; dc++) {
            ulonglong2 u = *(const ulonglong2*)(ui + dc * 4);
            #pragma unroll
            for (int jj = 0; jj < JT; jj++) {
                ulonglong2 v = *(const ulonglong2*)(ujb + jj * 68 + dc * 4);  // broadcast
                u64 p0 = f2_mul(u.x, v.x);
                u64 p1 = f2_mul(u.y, v.y);
                s1p[jj] = f2_add(s1p[jj], p0);
                s1p[jj] = f2_add(s1p[jj], p1);
                s2p[jj] = f2_fma(p0, p0, s2p[jj]);
                s2p[jj] = f2_fma(p1, p1, s2p[jj]);
            }
        }
    }

    float ra[JT], rb[JT], rc[JT], rd[JT];
    float cst[2 * JT];
    if (t < NI) {
        #pragma unroll
        for (int jj = 0; jj < JT; jj++) {
            float l1, h1, l2, h2;
            f2_unpack(s1p[jj], l1, h1);
            f2_unpack(s2p[jj], l2, h2);
            float mu  = (l1 + h1) * (1.f / DD);
            float var = fmaf(-mu, mu, (l2 + h2) * (1.f / DD));
            float rr  = rsqrtf(var + EPS);
            int j = jbase + jj;
            float s = q1 + kk1[j]; s = s > 0.f ? s : SLOPE * s;
            float a1 = __expf(s) * iZ1;
            float c1 = a1 * rr;
            s = q2 + kk2[j]; s = s > 0.f ? s : SLOPE * s;
            float a2 = __expf(s) * iZ2;
            float c2 = a2 * rr;
            cst[jj * 2 + 0] = c1; cst[jj * 2 + 1] = c2;
            ra[jj] = a1; rb[jj] = a2; rc[jj] = c1 * mu; rd[jj] = c2 * mu;
        }
        float* crow = c12 + t * 20;
        #pragma unroll
        for (int k = 0; k < 4; k++)
            *(float4*)(crow + k * 4) = make_float4(cst[k*4], cst[k*4+1], cst[k*4+2], cst[k*4+3]);
    } else {
        #pragma unroll
        for (int jj = 0; jj < JT; jj++) { ra[jj] = 0; rb[jj] = 0; rc[jj] = 0; rd[jj] = 0; }
    }

    #pragma unroll
    for (int jj = 0; jj < JT; jj++) {
        float v0 = ra[jj], v1 = rb[jj], v2 = rc[jj], v3 = rd[jj];
        #pragma unroll
        for (int o = 16; o > 0; o >>= 1) {
            v0 += __shfl_xor_sync(0xffffffffu, v0, o);
            v1 += __shfl_xor_sync(0xffffffffu, v1, o);
            v2 += __shfl_xor_sync(0xffffffffu, v2, o);
            v3 += __shfl_xor_sync(0xffffffffu, v3, o);
        }
        if (lane == 0) {
            red[warp * 32 + jj * 4 + 0] = v0;
            red[warp * 32 + jj * 4 + 1] = v1;
            red[warp * 32 + jj * 4 + 2] = v2;
            red[warp * 32 + jj * 4 + 3] = v3;
        }
    }
    __syncthreads();
    if (t < 32) {
        float s = 0.f;
        #pragma unroll
        for (int w = 0; w < 8; w++) s += red[w * 32 + t];
        Sc[t] = s;
    }
    __syncthreads();

    // ---- phase 2: warp (wj, ihalf): j-pair 2wj,2wj+1 over half the i range ----
    int wj    = warp & 3;
    int ihalf = warp >> 2;
    u64 a00 = 0, a01 = 0, a10 = 0, a11 = 0;   // [j0/j1][d0/d1], heads packed
    {
        int i0 = ihalf * 100;
        const float* up = ua_s + 2 * lane;
        const float* cp = c12 + wj * 4;
        #pragma unroll 4
        for (int i = i0; i < i0 + 100; i++) {
            float2 u = *(const float2*)(up + i * 68);
            ulonglong2 cq = *(const ulonglong2*)(cp + i * 20);  // broadcast 16B
            u64 ux = f2_pack(u.x, u.x);
            u64 uy = f2_pack(u.y, u.y);
            a00 = f2_fma(cq.x, ux, a00);
            a01 = f2_fma(cq.x, uy, a01);
            a10 = f2_fma(cq.y, ux, a10);
            a11 = f2_fma(cq.y, uy, a11);
        }
    }
    __syncthreads();                       // all c12 reads done
    u64* pbuf = (u64*)c12;                 // 4KB partial exchange (aliased)
    if (ihalf == 1) {
        u64* p = pbuf + ((size_t)(wj * 32 + lane)) * 4;
        p[0] = a00; p[1] = a01; p[2] = a10; p[3] = a11;
    }
    __syncthreads();
    if (ihalf == 0) {
        const u64* p = pbuf + ((size_t)(wj * 32 + lane)) * 4;
        a00 = f2_add(a00, p[0]);
        a01 = f2_add(a01, p[1]);
        a10 = f2_add(a10, p[2]);
        a11 = f2_add(a11, p[3]);
        float2 wl = *(const float2*)(wln + 2 * lane);
        float2 bl = *(const float2*)(bln + 2 * lane);
        #pragma unroll
        for (int k = 0; k < 2; k++) {
            int jj = 2 * wj + k;
            u64 S1x = k ? a10 : a00;
            u64 S1y = k ? a11 : a01;
            int j = jbase + jj;
            float2 uj = *(const float2*)(ua_s + j * 68 + 2 * lane);
            u64 S0  = f2_pack(Sc[jj * 4 + 0], Sc[jj * 4 + 1]);
            u64 S2n = f2_pack(-Sc[jj * 4 + 2], -Sc[jj * 4 + 3]);
            u64 X  = f2_fma(f2_pack(uj.x, uj.x), S1x, S2n);
            u64 at = f2_fma(f2_pack(bl.x, bl.x), S0, f2_mul(f2_pack(wl.x, wl.x), X));
            float t1, t2;
            f2_unpack(at, t1, t2);
            float ox = 0.5f * (t1 + t2);
            X  = f2_fma(f2_pack(uj.y, uj.y), S1y, S2n);
            at = f2_fma(f2_pack(bl.y, bl.y), S0, f2_mul(f2_pack(wl.y, wl.y), X));
            f2_unpack(at, t1, t2);
            float oy = 0.5f * (t1 + t2);
            ox = ox > 0.f ? ox : SLOPE * ox;
            oy = oy > 0.f ? oy : SLOPE * oy;
            *(float2*)(out + (size_t)(b * 201 + 1 + j) * DD + 2 * lane) = make_float2(ox, oy);
        }
    }
}

// ---------------- launch ----------------
extern "C" void kernel_launch(void* const* d_in, const int* in_sizes, int n_in,
                              void* d_out, int out_size) {
    const float* emb = (const float*)d_in[0];
    const float* lnw = (const float*)d_in[1];
    const float* lnb = (const float*)d_in[2];
    const float* W1  = (const float*)d_in[3];
    const float* W1b = (const float*)d_in[4];
    const float* W2  = (const float*)d_in[5];
    const float* W2b = (const float*)d_in[6];
    const float* a1  = (const float*)d_in[7];
    const float* a1b = (const float*)d_in[8];
    const float* a2  = (const float*)d_in[9];
    const float* a2b = (const float*)d_in[10];
    float* out = (float*)d_out;
    (void)in_sizes; (void)n_in; (void)out_size;

    cudaFuncSetAttribute(kA_prep, cudaFuncAttributeMaxDynamicSharedMemorySize, A_BYTES);
    cudaFuncSetAttribute(k3_main, cudaFuncAttributeMaxDynamicSharedMemorySize, SMEM_BYTES);

    dim3 gA(2, BN);
    kA_prep<<<gA, 256, A_BYTES>>>(emb, lnw, lnb, W1, W1b, W2, W2b,
                                  a1, a1b, a2, a2b, out);
    dim3 g3(NTILES, BN);
    k3_main<<<g3, 256, SMEM_BYTES>>>(lnw, lnb, out);
}

// round 6
// speedup vs baseline: 1.2369x; 1.0156x over previous
#include <cuda_runtime.h>
#include <math.h>

#define BN    32
#define NODES 202
#define NI    200
#define DD    64
#define JT    8
#define NTILES (NI/JT)   // 25
#define EPS   1e-5f
#define SLOPE 0.01f

typedef unsigned long long u64;

// ---- packed fp32x2 helpers (sm_103a) ----
__device__ __forceinline__ u64 f2_mul(u64 a, u64 b) {
    u64 r; asm("mul.rn.f32x2 %0,%1,%2;" : "=l"(r) : "l"(a), "l"(b)); return r;
}
__device__ __forceinline__ u64 f2_add(u64 a, u64 b) {
    u64 r; asm("add.rn.f32x2 %0,%1,%2;" : "=l"(r) : "l"(a), "l"(b)); return r;
}
__device__ __forceinline__ u64 f2_fma(u64 a, u64 b, u64 c) {
    u64 r; asm("fma.rn.f32x2 %0,%1,%2,%3;" : "=l"(r) : "l"(a), "l"(b), "l"(c)); return r;
}
__device__ __forceinline__ u64 f2_pack(float lo, float hi) {
    u64 r; asm("mov.b64 %0,{%1,%2};" : "=l"(r) : "f"(lo), "f"(hi)); return r;
}
__device__ __forceinline__ void f2_unpack(u64 v, float& lo, float& hi) {
    asm("mov.b64 {%0,%1},%2;" : "=f"(lo), "=f"(hi) : "l"(v));
}

// ---------------- device scratch ----------------
__device__ float g_ua[BN * NI * DD];
__device__ float g_prm[BN * NI * 8];     // (q1,k1,iZ1,q2),(k2,iZ2,_,_)

// =======================================================================
// kA: per-batch prep. grid (4, BN), 256 threads.
#define A_W    0        // 8192  W_s[h*4096+o*64+d]
#define A_A    8192     // 384
#define A_WB   8576     // 128
#define A_LNW  8704     // 64
#define A_LNB  8768     // 64
#define A_RAW  8832     // 202*68 = 13736
#define A_UAK  22568    // 200*68 = 13600
#define A_MU   36168    // 202
#define A_RS   36370    // 202
#define A_UID  36572    // 64
#define A_IID  36636    // 64
#define A_VQ   36700    // 128
#define A_VK   36828    // 128
#define A_SKA  36956    // 400 (k1[200],k2[200])
#define A_SQ   37356    // 400 (q1[200],q2[200])
#define A_ZP   37756    // 400
#define A_RED  38156    // 8
#define A_CQK  38164    // 6
#define A_QC   38170    // 2
#define A_KC   38172    // 2
#define A_FLOATS 38174
#define A_BYTES  (A_FLOATS * 4)

extern __shared__ float smA[];

__global__ __launch_bounds__(256, 1)
void kA_prep(const float* __restrict__ emb,
             const float* __restrict__ lnw, const float* __restrict__ lnb,
             const float* __restrict__ W1, const float* __restrict__ W1b,
             const float* __restrict__ W2, const float* __restrict__ W2b,
             const float* __restrict__ a1, const float* __restrict__ a1b,
             const float* __restrict__ a2, const float* __restrict__ a2b,
             float* __restrict__ out) {
    int q    = blockIdx.x;        // quarter 0..3
    int b    = blockIdx.y;
    int t    = threadIdx.x;
    int warp = t >> 5, lane = t & 31;

    float* W_s   = smA + A_W;
    float* a_s   = smA + A_A;
    float* wb_s  = smA + A_WB;
    float* lnw_s = smA + A_LNW;
    float* lnb_s = smA + A_LNB;
    float* raw   = smA + A_RAW;   // stride 68
    float* ua_s  = smA + A_UAK;   // stride 68
    float* mu_s  = smA + A_MU;
    float* rs_s  = smA + A_RS;
    float* uid   = smA + A_UID;
    float* iid   = smA + A_IID;
    float* vq_s  = smA + A_VQ;
    float* vk_s  = smA + A_VK;
    float* sk    = smA + A_SKA;
    float* sq    = smA + A_SQ;
    float* zp    = smA + A_ZP;
    float* red   = smA + A_RED;
    float* cqk   = smA + A_CQK;
    float* qc_s  = smA + A_QC;
    float* kc_s  = smA + A_KC;

    // ---- P0: stage everything ----
    for (int idx = t; idx < 2048; idx += 256) {
        int h = idx >> 10;
        ((float4*)W_s)[idx] = ((const float4*)(h ? W2 : W1))[idx & 1023];
    }
    for (int idx = t; idx < 384; idx += 256)
        a_s[idx] = (idx < 192) ? a1[idx] : a2[idx - 192];
    if (t < 128) wb_s[t] = (t < 64) ? W1b[t] : W2b[t - 64];
    if (t < 64) { lnw_s[t] = lnw[t]; lnb_s[t] = lnb[t]; }
    const float4* e4 = (const float4*)(emb + (size_t)b * NODES * DD);
    for (int idx = t; idx < NODES * 16; idx += 256) {
        int r = idx >> 4, c = idx & 15;
        *(float4*)(raw + r * 68 + c * 4) = e4[idx];
    }
    __syncthreads();

    // ---- P1: per-row stats (thread-per-row) + bias dots ----
    if (t < NODES) {
        const float* rp = raw + t * 68;
        float s = 0.f, ss = 0.f;
        #pragma unroll
        for (int c = 0; c < 16; c++) {
            float4 v = *(const float4*)(rp + c * 4);
            s += (v.x + v.y) + (v.z + v.w);
            ss = fmaf(v.x, v.x, fmaf(v.y, v.y, fmaf(v.z, v.z, fmaf(v.w, v.w, ss))));
        }
        float m = s * (1.f / DD);
        float var = fmaf(-m, m, ss * (1.f / DD));
        mu_s[t] = m;
        rs_s[t] = rsqrtf(var + EPS);
    }
    if (t >= 208 && t < 214) {
        int idx = t - 208, h = idx / 3, wch = idx % 3;
        float s = 0.f;
        #pragma unroll 8
        for (int o = 0; o < DD; o++)
            s = fmaf(a_s[h * 192 + wch * 64 + o], wb_s[h * 64 + o], s);
        cqk[idx] = s;
    }
    __syncthreads();

    // ---- P2: uid / iid ----
    if (t < 128) {
        int rw = t >> 6, d = t & 63;
        float v = fmaf((raw[rw * 68 + d] - mu_s[rw]) * rs_s[rw], lnw_s[d], lnb_s[d]);
        (rw ? iid : uid)[d] = v;
    }
    __syncthreads();
    if (q == 0 && t < DD) {
        float u = uid[t] * iid[t];
        out[(size_t)(b * 201) * DD + t] = u > 0.f ? u : SLOPE * u;
    }

    // ---- P3: vectorized ua pass (full smem, quarter gmem write) ----
    for (int idx = t; idx < NI * 16; idx += 256) {
        int r = idx >> 4, c = idx & 15;
        float4 v = *(const float4*)(raw + (r + 2) * 68 + c * 4);
        float m = mu_s[r + 2], sc = rs_s[r + 2];
        float4 w4 = *(const float4*)(lnw_s + c * 4);
        float4 b4 = *(const float4*)(lnb_s + c * 4);
        float4 u4 = *(const float4*)(uid + c * 4);
        float4 o4;
        o4.x = fmaf((v.x - m) * sc, w4.x, b4.x) * u4.x;
        o4.y = fmaf((v.y - m) * sc, w4.y, b4.y) * u4.y;
        o4.z = fmaf((v.z - m) * sc, w4.z, b4.z) * u4.z;
        o4.w = fmaf((v.w - m) * sc, w4.w, b4.w) * u4.w;
        *(float4*)(ua_s + r * 68 + c * 4) = o4;
        if (r >= q * 50 && r < q * 50 + 50)
            ((float4*)(g_ua + ((size_t)b * NI + r) * DD))[c] = o4;
    }
    __syncthreads();

    // ---- P4: fold vq/vk + vi.iid ----
    if (t < 128) {
        int h = t >> 6, d = t & 63;
        const float* Wp = W_s + h * 4096 + d;
        const float* ap = a_s + h * 192;
        float sqv = 0.f, skv = 0.f, siv = 0.f;
        #pragma unroll 8
        for (int o = 0; o < DD; o++) {
            float wv = Wp[o * 64];
            sqv = fmaf(ap[o],        wv, sqv);
            skv = fmaf(ap[64 + o],   wv, skv);
            siv = fmaf(ap[128 + o],  wv, siv);
        }
        vq_s[h * 64 + d] = sqv;
        vk_s[h * 64 + d] = skv;
        float viid = siv * iid[d];
        #pragma unroll
        for (int o = 16; o > 0; o >>= 1) viid += __shfl_xor_sync(0xffffffffu, viid, o);
        if (lane == 0) red[warp] = viid;
    }
    __syncthreads();
    if (t == 0) {
        qc_s[0] = red[0] + red[1] + cqk[0] + cqk[2] + a1b[0];
        kc_s[0] = cqk[1];
        qc_s[1] = red[2] + red[3] + cqk[3] + cqk[5] + a2b[0];
        kc_s[1] = cqk[4];
    }
    __syncthreads();

    // ---- P5: q/k dots, d-outer float4 (conflict-free) ----
    if (t < NI) {
        const float* u = ua_s + t * 68;
        float s10 = 0, s20 = 0, s11 = 0, s21 = 0;
        #pragma unroll
        for (int c = 0; c < 16; c++) {
            float4 uv = *(const float4*)(u + c * 4);
            float4 q0 = *(const float4*)(vq_s + c * 4);
            float4 k0 = *(const float4*)(vk_s + c * 4);
            float4 q1v = *(const float4*)(vq_s + 64 + c * 4);
            float4 k1v = *(const float4*)(vk_s + 64 + c * 4);
            s10 = fmaf(uv.x, q0.x, fmaf(uv.y, q0.y, fmaf(uv.z, q0.z, fmaf(uv.w, q0.w, s10))));
            s20 = fmaf(uv.x, k0.x, fmaf(uv.y, k0.y, fmaf(uv.z, k0.z, fmaf(uv.w, k0.w, s20))));
            s11 = fmaf(uv.x, q1v.x, fmaf(uv.y, q1v.y, fmaf(uv.z, q1v.z, fmaf(uv.w, q1v.w, s11))));
            s21 = fmaf(uv.x, k1v.x, fmaf(uv.y, k1v.y, fmaf(uv.z, k1v.z, fmaf(uv.w, k1v.w, s21))));
        }
        sq[t]       = s10 + qc_s[0];
        sq[200 + t] = s11 + qc_s[1];
        sk[t]       = s20 + kc_s[0];
        sk[200 + t] = s21 + kc_s[1];
    }
    __syncthreads();

    // ---- P6: Z partials — 4 j-segments of 50, over this block's 50 i ----
    if (t < 200) {
        int seg = t / 50, il = t % 50;
        int i = q * 50 + il;
        float q1 = sq[i], q2 = sq[200 + i];
        float Z1 = 0.f, Z2 = 0.f;
        int j0 = seg * 50;
        #pragma unroll 5
        for (int jj = 0; jj < 50; jj++) {
            int j = j0 + jj;
            float s = q1 + sk[j];       s = s > 0.f ? s : SLOPE * s; Z1 += __expf(s);
            float r = q2 + sk[200 + j]; r = r > 0.f ? r : SLOPE * r; Z2 += __expf(r);
        }
        zp[seg * 50 + il]       = Z1;
        zp[200 + seg * 50 + il] = Z2;
    }
    __syncthreads();
    if (t < 50) {
        int i = q * 50 + t;
        float Z1 = zp[t] + zp[50 + t] + zp[100 + t] + zp[150 + t];
        float Z2 = zp[200 + t] + zp[250 + t] + zp[300 + t] + zp[350 + t];
        float4* p = (float4*)(g_prm + (size_t)(b * NI + i) * 8);
        p[0] = make_float4(sq[i], sk[i], 1.f / Z1, sq[200 + i]);
        p[1] = make_float4(sk[200 + i], 1.f / Z2, 0.f, 0.f);
    }
}

// =======================================================================
// K3: main fused pair kernel
// c12 layout: 4 planes of [i]->float4 {c1(2k),c2(2k),c1(2k+1),c2(2k+1)}
#define OFF_UA   0
#define OFF_KK1  13600
#define OFF_KK2  13800
#define OFF_C12  14000     // 4*800 = 3200
#define OFF_WLN  17200
#define OFF_BLN  17264
#define OFF_SC   17328
#define OFF_RED  17360
#define SMEM_FLOATS (OFF_RED + 256)   // 17616
#define SMEM_BYTES  (SMEM_FLOATS * 4)

extern __shared__ float sm3[];

__global__ __launch_bounds__(256, 3)
void k3_main(const float* __restrict__ lnw, const float* __restrict__ lnb,
             float* __restrict__ out) {
    int jt = blockIdx.x;
    int b  = blockIdx.y;
    int t  = threadIdx.x;
    int warp = t >> 5, lane = t & 31;

    float* ua_s = sm3 + OFF_UA;     // stride 68
    float* kk1  = sm3 + OFF_KK1;
    float* kk2  = sm3 + OFF_KK2;
    float* c12  = sm3 + OFF_C12;    // planes of 800
    float* wln  = sm3 + OFF_WLN;
    float* bln  = sm3 + OFF_BLN;
    float* Sc   = sm3 + OFF_SC;
    float* red  = sm3 + OFF_RED;

    const float4* uab4 = (const float4*)(g_ua + (size_t)b * NI * DD);
    for (int idx = t; idx < NI * 16; idx += 256) {
        int i = idx >> 4, c = idx & 15;
        *(float4*)(ua_s + i * 68 + c * 4) = uab4[idx];
    }
    if (t < 64) { wln[t] = lnw[t]; bln[t] = lnb[t]; }

    float q1 = 0, iZ1 = 0, q2 = 0, iZ2 = 0;
    if (t < NI) {
        const float4* pp = (const float4*)(g_prm + (size_t)(b * NI + t) * 8);
        float4 p0 = pp[0], p1 = pp[1];
        q1 = p0.x; kk1[t] = p0.y; iZ1 = p0.z; q2 = p0.w;
        kk2[t] = p1.x; iZ2 = p1.y;
    }
    __syncthreads();

    int jbase = jt * JT;

    // ---- phase 1: Gram stats (packed f32x2, j-register-tiled) ----
    u64 s1p[JT], s2p[JT];
    #pragma unroll
    for (int jj = 0; jj < JT; jj++) { s1p[jj] = 0ull; s2p[jj] = 0ull; }

    if (t < NI) {
        const float* ui = ua_s + t * 68;
        const float* ujb = ua_s + jbase * 68;
        #pragma unroll 4
        for (int dc = 0; dc < 16; dc++) {
            ulonglong2 u = *(const ulonglong2*)(ui + dc * 4);
            #pragma unroll
            for (int jj = 0; jj < JT; jj++) {
                ulonglong2 v = *(const ulonglong2*)(ujb + jj * 68 + dc * 4);  // broadcast
                u64 p0 = f2_mul(u.x, v.x);
                u64 p1 = f2_mul(u.y, v.y);
                s1p[jj] = f2_add(s1p[jj], p0);
                s1p[jj] = f2_add(s1p[jj], p1);
                s2p[jj] = f2_fma(p0, p0, s2p[jj]);
                s2p[jj] = f2_fma(p1, p1, s2p[jj]);
            }
        }
    }

    float ra[JT], rb[JT], rc[JT], rd[JT];
    float cst[2 * JT];
    if (t < NI) {
        #pragma unroll
        for (int jj = 0; jj < JT; jj++) {
            float l1, h1, l2, h2;
            f2_unpack(s1p[jj], l1, h1);
            f2_unpack(s2p[jj], l2, h2);
            float mu  = (l1 + h1) * (1.f / DD);
            float var = fmaf(-mu, mu, (l2 + h2) * (1.f / DD));
            float rr  = rsqrtf(var + EPS);
            int j = jbase + jj;
            float s = q1 + kk1[j]; s = s > 0.f ? s : SLOPE * s;
            float a1 = __expf(s) * iZ1;
            float c1 = a1 * rr;
            s = q2 + kk2[j]; s = s > 0.f ? s : SLOPE * s;
            float a2 = __expf(s) * iZ2;
            float c2 = a2 * rr;
            cst[jj * 2 + 0] = c1; cst[jj * 2 + 1] = c2;
            ra[jj] = a1; rb[jj] = a2; rc[jj] = c1 * mu; rd[jj] = c2 * mu;
        }
        float* crow = c12 + t * 4;
        #pragma unroll
        for (int k = 0; k < 4; k++)
            *(float4*)(crow + k * 800) = make_float4(cst[k*4], cst[k*4+1], cst[k*4+2], cst[k*4+3]);
    } else {
        #pragma unroll
        for (int jj = 0; jj < JT; jj++) { ra[jj] = 0; rb[jj] = 0; rc[jj] = 0; rd[jj] = 0; }
    }

    #pragma unroll
    for (int jj = 0; jj < JT; jj++) {
        float v0 = ra[jj], v1 = rb[jj], v2 = rc[jj], v3 = rd[jj];
        #pragma unroll
        for (int o = 16; o > 0; o >>= 1) {
            v0 += __shfl_xor_sync(0xffffffffu, v0, o);
            v1 += __shfl_xor_sync(0xffffffffu, v1, o);
            v2 += __shfl_xor_sync(0xffffffffu, v2, o);
            v3 += __shfl_xor_sync(0xffffffffu, v3, o);
        }
        if (lane == 0) {
            red[warp * 32 + jj * 4 + 0] = v0;
            red[warp * 32 + jj * 4 + 1] = v1;
            red[warp * 32 + jj * 4 + 2] = v2;
            red[warp * 32 + jj * 4 + 3] = v3;
        }
    }
    __syncthreads();
    if (t < 32) {
        float s = 0.f;
        #pragma unroll
        for (int w = 0; w < 8; w++) s += red[w * 32 + t];
        Sc[t] = s;
    }
    __syncthreads();

    // ---- phase 2: warp (wj, ihalf): j-pair 2wj,2wj+1 over half the i range ----
    int wj    = warp & 3;
    int ihalf = warp >> 2;
    u64 a00 = 0, a01 = 0, a10 = 0, a11 = 0;   // [j0/j1][d0/d1], heads packed
    {
        int i0 = ihalf * 100;
        const float* up = ua_s + 2 * lane;
        const float* cp = c12 + wj * 800;
        #pragma unroll 4
        for (int i = i0; i < i0 + 100; i++) {
            float2 u = *(const float2*)(up + i * 68);
            ulonglong2 cq = *(const ulonglong2*)(cp + i * 4);  // broadcast 16B
            u64 ux = f2_pack(u.x, u.x);
            u64 uy = f2_pack(u.y, u.y);
            a00 = f2_fma(cq.x, ux, a00);
            a01 = f2_fma(cq.x, uy, a01);
            a10 = f2_fma(cq.y, ux, a10);
            a11 = f2_fma(cq.y, uy, a11);
        }
    }
    __syncthreads();                       // all c12 reads done
    u64* pbuf = (u64*)c12;                 // 4KB partial exchange (aliased)
    if (ihalf == 1) {
        u64* p = pbuf + ((size_t)(wj * 32 + lane)) * 4;
        p[0] = a00; p[1] = a01; p[2] = a10; p[3] = a11;
    }
    __syncthreads();
    if (ihalf == 0) {
        const u64* p = pbuf + ((size_t)(wj * 32 + lane)) * 4;
        a00 = f2_add(a00, p[0]);
        a01 = f2_add(a01, p[1]);
        a10 = f2_add(a10, p[2]);
        a11 = f2_add(a11, p[3]);
        float2 wl = *(const float2*)(wln + 2 * lane);
        float2 bl = *(const float2*)(bln + 2 * lane);
        #pragma unroll
        for (int k = 0; k < 2; k++) {
            int jj = 2 * wj + k;
            u64 S1x = k ? a10 : a00;
            u64 S1y = k ? a11 : a01;
            int j = jbase + jj;
            float2 uj = *(const float2*)(ua_s + j * 68 + 2 * lane);
            u64 S0  = f2_pack(Sc[jj * 4 + 0], Sc[jj * 4 + 1]);
            u64 S2n = f2_pack(-Sc[jj * 4 + 2], -Sc[jj * 4 + 3]);
            u64 X  = f2_fma(f2_pack(uj.x, uj.x), S1x, S2n);
            u64 at = f2_fma(f2_pack(bl.x, bl.x), S0, f2_mul(f2_pack(wl.x, wl.x), X));
            float t1, t2;
            f2_unpack(at, t1, t2);
            float ox = 0.5f * (t1 + t2);
            X  = f2_fma(f2_pack(uj.y, uj.y), S1y, S2n);
            at = f2_fma(f2_pack(bl.y, bl.y), S0, f2_mul(f2_pack(wl.y, wl.y), X));
            f2_unpack(at, t1, t2);
            float oy = 0.5f * (t1 + t2);
            ox = ox > 0.f ? ox : SLOPE * ox;
            oy = oy > 0.f ? oy : SLOPE * oy;
            *(float2*)(out + (size_t)(b * 201 + 1 + j) * DD + 2 * lane) = make_float2(ox, oy);
        }
    }
}

// ---------------- launch ----------------
extern "C" void kernel_launch(void* const* d_in, const int* in_sizes, int n_in,
                              void* d_out, int out_size) {
    const float* emb = (const float*)d_in[0];
    const float* lnw = (const float*)d_in[1];
    const float* lnb = (const float*)d_in[2];
    const float* W1  = (const float*)d_in[3];
    const float* W1b = (const float*)d_in[4];
    const float* W2  = (const float*)d_in[5];
    const float* W2b = (const float*)d_in[6];
    const float* a1  = (const float*)d_in[7];
    const float* a1b = (const float*)d_in[8];
    const float* a2  = (const float*)d_in[9];
    const float* a2b = (const float*)d_in[10];
    float* out = (float*)d_out;
    (void)in_sizes; (void)n_in; (void)out_size;

    cudaFuncSetAttribute(kA_prep, cudaFuncAttributeMaxDynamicSharedMemorySize, A_BYTES);
    cudaFuncSetAttribute(k3_main, cudaFuncAttributeMaxDynamicSharedMemorySize, SMEM_BYTES);

    dim3 gA(4, BN);
    kA_prep<<<gA, 256, A_BYTES>>>(emb, lnw, lnb, W1, W1b, W2, W2b,
                                  a1, a1b, a2, a2b, out);
    dim3 g3(NTILES, BN);
    k3_main<<<g3, 256, SMEM_BYTES>>>(lnw, lnb, out);
}

// round 7
// speedup vs baseline: 1.2938x; 1.0460x over previous
#include <cuda_runtime.h>
#include <math.h>

#define BN    32
#define NODES 202
#define NI    200
#define DD    64
#define JT    8
#define NTILES (NI/JT)   // 25
#define EPS   1e-5f
#define SLOPE 0.01f

typedef unsigned long long u64;

// ---- packed fp32x2 helpers (sm_103a) ----
__device__ __forceinline__ u64 f2_mul(u64 a, u64 b) {
    u64 r; asm("mul.rn.f32x2 %0,%1,%2;" : "=l"(r) : "l"(a), "l"(b)); return r;
}
__device__ __forceinline__ u64 f2_add(u64 a, u64 b) {
    u64 r; asm("add.rn.f32x2 %0,%1,%2;" : "=l"(r) : "l"(a), "l"(b)); return r;
}
__device__ __forceinline__ u64 f2_fma(u64 a, u64 b, u64 c) {
    u64 r; asm("fma.rn.f32x2 %0,%1,%2,%3;" : "=l"(r) : "l"(a), "l"(b), "l"(c)); return r;
}
__device__ __forceinline__ u64 f2_pack(float lo, float hi) {
    u64 r; asm("mov.b64 %0,{%1,%2};" : "=l"(r) : "f"(lo), "f"(hi)); return r;
}
__device__ __forceinline__ void f2_unpack(u64 v, float& lo, float& hi) {
    asm("mov.b64 {%0,%1},%2;" : "=f"(lo), "=f"(hi) : "l"(v));
}

// ---------------- device scratch ----------------
__device__ float g_ua[BN * NI * DD];
__device__ float g_prm[BN * NI * 8];     // (q1,k1,iZ1,q2),(k2,iZ2,_,_)

// =======================================================================
// kA: per-batch prep. grid (4, BN), 256 threads.  (unchanged from R6)
#define A_W    0
#define A_A    8192
#define A_WB   8576
#define A_LNW  8704
#define A_LNB  8768
#define A_RAW  8832
#define A_UAK  22568
#define A_MU   36168
#define A_RS   36370
#define A_UID  36572
#define A_IID  36636
#define A_VQ   36700
#define A_VK   36828
#define A_SKA  36956
#define A_SQ   37356
#define A_ZP   37756
#define A_RED  38156
#define A_CQK  38164
#define A_QC   38170
#define A_KC   38172
#define A_FLOATS 38174
#define A_BYTES  (A_FLOATS * 4)

extern __shared__ float smA[];

__global__ __launch_bounds__(256, 1)
void kA_prep(const float* __restrict__ emb,
             const float* __restrict__ lnw, const float* __restrict__ lnb,
             const float* __restrict__ W1, const float* __restrict__ W1b,
             const float* __restrict__ W2, const float* __restrict__ W2b,
             const float* __restrict__ a1, const float* __restrict__ a1b,
             const float* __restrict__ a2, const float* __restrict__ a2b,
             float* __restrict__ out) {
    int q    = blockIdx.x;
    int b    = blockIdx.y;
    int t    = threadIdx.x;
    int warp = t >> 5, lane = t & 31;

    float* W_s   = smA + A_W;
    float* a_s   = smA + A_A;
    float* wb_s  = smA + A_WB;
    float* lnw_s = smA + A_LNW;
    float* lnb_s = smA + A_LNB;
    float* raw   = smA + A_RAW;
    float* ua_s  = smA + A_UAK;
    float* mu_s  = smA + A_MU;
    float* rs_s  = smA + A_RS;
    float* uid   = smA + A_UID;
    float* iid   = smA + A_IID;
    float* vq_s  = smA + A_VQ;
    float* vk_s  = smA + A_VK;
    float* sk    = smA + A_SKA;
    float* sq    = smA + A_SQ;
    float* zp    = smA + A_ZP;
    float* red   = smA + A_RED;
    float* cqk   = smA + A_CQK;
    float* qc_s  = smA + A_QC;
    float* kc_s  = smA + A_KC;

    for (int idx = t; idx < 2048; idx += 256) {
        int h = idx >> 10;
        ((float4*)W_s)[idx] = ((const float4*)(h ? W2 : W1))[idx & 1023];
    }
    for (int idx = t; idx < 384; idx += 256)
        a_s[idx] = (idx < 192) ? a1[idx] : a2[idx - 192];
    if (t < 128) wb_s[t] = (t < 64) ? W1b[t] : W2b[t - 64];
    if (t < 64) { lnw_s[t] = lnw[t]; lnb_s[t] = lnb[t]; }
    const float4* e4 = (const float4*)(emb + (size_t)b * NODES * DD);
    for (int idx = t; idx < NODES * 16; idx += 256) {
        int r = idx >> 4, c = idx & 15;
        *(float4*)(raw + r * 68 + c * 4) = e4[idx];
    }
    __syncthreads();

    if (t < NODES) {
        const float* rp = raw + t * 68;
        float s = 0.f, ss = 0.f;
        #pragma unroll
        for (int c = 0; c < 16; c++) {
            float4 v = *(const float4*)(rp + c * 4);
            s += (v.x + v.y) + (v.z + v.w);
            ss = fmaf(v.x, v.x, fmaf(v.y, v.y, fmaf(v.z, v.z, fmaf(v.w, v.w, ss))));
        }
        float m = s * (1.f / DD);
        float var = fmaf(-m, m, ss * (1.f / DD));
        mu_s[t] = m;
        rs_s[t] = rsqrtf(var + EPS);
    }
    if (t >= 208 && t < 214) {
        int idx = t - 208, h = idx / 3, wch = idx % 3;
        float s = 0.f;
        #pragma unroll 8
        for (int o = 0; o < DD; o++)
            s = fmaf(a_s[h * 192 + wch * 64 + o], wb_s[h * 64 + o], s);
        cqk[idx] = s;
    }
    __syncthreads();

    if (t < 128) {
        int rw = t >> 6, d = t & 63;
        float v = fmaf((raw[rw * 68 + d] - mu_s[rw]) * rs_s[rw], lnw_s[d], lnb_s[d]);
        (rw ? iid : uid)[d] = v;
    }
    __syncthreads();
    if (q == 0 && t < DD) {
        float u = uid[t] * iid[t];
        out[(size_t)(b * 201) * DD + t] = u > 0.f ? u : SLOPE * u;
    }

    for (int idx = t; idx < NI * 16; idx += 256) {
        int r = idx >> 4, c = idx & 15;
        float4 v = *(const float4*)(raw + (r + 2) * 68 + c * 4);
        float m = mu_s[r + 2], sc = rs_s[r + 2];
        float4 w4 = *(const float4*)(lnw_s + c * 4);
        float4 b4 = *(const float4*)(lnb_s + c * 4);
        float4 u4 = *(const float4*)(uid + c * 4);
        float4 o4;
        o4.x = fmaf((v.x - m) * sc, w4.x, b4.x) * u4.x;
        o4.y = fmaf((v.y - m) * sc, w4.y, b4.y) * u4.y;
        o4.z = fmaf((v.z - m) * sc, w4.z, b4.z) * u4.z;
        o4.w = fmaf((v.w - m) * sc, w4.w, b4.w) * u4.w;
        *(float4*)(ua_s + r * 68 + c * 4) = o4;
        if (r >= q * 50 && r < q * 50 + 50)
            ((float4*)(g_ua + ((size_t)b * NI + r) * DD))[c] = o4;
    }
    __syncthreads();

    if (t < 128) {
        int h = t >> 6, d = t & 63;
        const float* Wp = W_s + h * 4096 + d;
        const float* ap = a_s + h * 192;
        float sqv = 0.f, skv = 0.f, siv = 0.f;
        #pragma unroll 8
        for (int o = 0; o < DD; o++) {
            float wv = Wp[o * 64];
            sqv = fmaf(ap[o],        wv, sqv);
            skv = fmaf(ap[64 + o],   wv, skv);
            siv = fmaf(ap[128 + o],  wv, siv);
        }
        vq_s[h * 64 + d] = sqv;
        vk_s[h * 64 + d] = skv;
        float viid = siv * iid[d];
        #pragma unroll
        for (int o = 16; o > 0; o >>= 1) viid += __shfl_xor_sync(0xffffffffu, viid, o);
        if (lane == 0) red[warp] = viid;
    }
    __syncthreads();
    if (t == 0) {
        qc_s[0] = red[0] + red[1] + cqk[0] + cqk[2] + a1b[0];
        kc_s[0] = cqk[1];
        qc_s[1] = red[2] + red[3] + cqk[3] + cqk[5] + a2b[0];
        kc_s[1] = cqk[4];
    }
    __syncthreads();

    if (t < NI) {
        const float* u = ua_s + t * 68;
        float s10 = 0, s20 = 0, s11 = 0, s21 = 0;
        #pragma unroll
        for (int c = 0; c < 16; c++) {
            float4 uv = *(const float4*)(u + c * 4);
            float4 q0 = *(const float4*)(vq_s + c * 4);
            float4 k0 = *(const float4*)(vk_s + c * 4);
            float4 q1v = *(const float4*)(vq_s + 64 + c * 4);
            float4 k1v = *(const float4*)(vk_s + 64 + c * 4);
            s10 = fmaf(uv.x, q0.x, fmaf(uv.y, q0.y, fmaf(uv.z, q0.z, fmaf(uv.w, q0.w, s10))));
            s20 = fmaf(uv.x, k0.x, fmaf(uv.y, k0.y, fmaf(uv.z, k0.z, fmaf(uv.w, k0.w, s20))));
            s11 = fmaf(uv.x, q1v.x, fmaf(uv.y, q1v.y, fmaf(uv.z, q1v.z, fmaf(uv.w, q1v.w, s11))));
            s21 = fmaf(uv.x, k1v.x, fmaf(uv.y, k1v.y, fmaf(uv.z, k1v.z, fmaf(uv.w, k1v.w, s21))));
        }
        sq[t]       = s10 + qc_s[0];
        sq[200 + t] = s11 + qc_s[1];
        sk[t]       = s20 + kc_s[0];
        sk[200 + t] = s21 + kc_s[1];
    }
    __syncthreads();

    if (t < 200) {
        int seg = t / 50, il = t % 50;
        int i = q * 50 + il;
        float q1 = sq[i], q2 = sq[200 + i];
        float Z1 = 0.f, Z2 = 0.f;
        int j0 = seg * 50;
        #pragma unroll 5
        for (int jj = 0; jj < 50; jj++) {
            int j = j0 + jj;
            float s = q1 + sk[j];       s = s > 0.f ? s : SLOPE * s; Z1 += __expf(s);
            float r = q2 + sk[200 + j]; r = r > 0.f ? r : SLOPE * r; Z2 += __expf(r);
        }
        zp[seg * 50 + il]       = Z1;
        zp[200 + seg * 50 + il] = Z2;
    }
    __syncthreads();
    if (t < 50) {
        int i = q * 50 + t;
        float Z1 = zp[t] + zp[50 + t] + zp[100 + t] + zp[150 + t];
        float Z2 = zp[200 + t] + zp[250 + t] + zp[300 + t] + zp[350 + t];
        float4* p = (float4*)(g_prm + (size_t)(b * NI + i) * 8);
        p[0] = make_float4(sq[i], sk[i], 1.f / Z1, sq[200 + i]);
        p[1] = make_float4(sk[200 + i], 1.f / Z2, 0.f, 0.f);
    }
}

// =======================================================================
// K3: main fused pair kernel.  S2 derived from S1 in epilogue.
#define OFF_UA   0
#define OFF_KK1  13600
#define OFF_KK2  13800
#define OFF_C12  14000     // 4*800 = 3200
#define OFF_WLN  17200
#define OFF_BLN  17264
#define OFF_SC   17328     // 16 (S0 only)
#define OFF_RED  17360     // 128
#define SMEM_FLOATS (OFF_RED + 128)   // 17488
#define SMEM_BYTES  (SMEM_FLOATS * 4)

extern __shared__ float sm3[];

__global__ __launch_bounds__(256, 3)
void k3_main(const float* __restrict__ lnw, const float* __restrict__ lnb,
             float* __restrict__ out) {
    int jt = blockIdx.x;
    int b  = blockIdx.y;
    int t  = threadIdx.x;
    int warp = t >> 5, lane = t & 31;

    float* ua_s = sm3 + OFF_UA;     // stride 68
    float* kk1  = sm3 + OFF_KK1;
    float* kk2  = sm3 + OFF_KK2;
    float* c12  = sm3 + OFF_C12;    // planes of 800
    float* wln  = sm3 + OFF_WLN;
    float* bln  = sm3 + OFF_BLN;
    float* Sc   = sm3 + OFF_SC;     // S0: [jj*2 + head]
    float* red  = sm3 + OFF_RED;

    const float4* uab4 = (const float4*)(g_ua + (size_t)b * NI * DD);
    for (int idx = t; idx < NI * 16; idx += 256) {
        int i = idx >> 4, c = idx & 15;
        *(float4*)(ua_s + i * 68 + c * 4) = uab4[idx];
    }
    if (t < 64) { wln[t] = lnw[t]; bln[t] = lnb[t]; }

    float q1 = 0, iZ1 = 0, q2 = 0, iZ2 = 0;
    if (t < NI) {
        const float4* pp = (const float4*)(g_prm + (size_t)(b * NI + t) * 8);
        float4 p0 = pp[0], p1 = pp[1];
        q1 = p0.x; kk1[t] = p0.y; iZ1 = p0.z; q2 = p0.w;
        kk2[t] = p1.x; iZ2 = p1.y;
    }
    __syncthreads();

    int jbase = jt * JT;

    // ---- phase 1: Gram stats (packed f32x2, j-register-tiled) ----
    u64 s1p[JT], s2p[JT];
    #pragma unroll
    for (int jj = 0; jj < JT; jj++) { s1p[jj] = 0ull; s2p[jj] = 0ull; }

    if (t < NI) {
        const float* ui = ua_s + t * 68;
        const float* ujb = ua_s + jbase * 68;
        #pragma unroll 4
        for (int dc = 0; dc < 16; dc++) {
            ulonglong2 u = *(const ulonglong2*)(ui + dc * 4);
            #pragma unroll
            for (int jj = 0; jj < JT; jj++) {
                ulonglong2 v = *(const ulonglong2*)(ujb + jj * 68 + dc * 4);  // broadcast
                u64 p0 = f2_mul(u.x, v.x);
                u64 p1 = f2_mul(u.y, v.y);
                s1p[jj] = f2_add(s1p[jj], p0);
                s1p[jj] = f2_add(s1p[jj], p1);
                s2p[jj] = f2_fma(p0, p0, s2p[jj]);
                s2p[jj] = f2_fma(p1, p1, s2p[jj]);
            }
        }
    }

    // per-jj epilogue: alpha, c = alpha*rr  (S0 reduction inputs only)
    float ra[JT], rb[JT];
    float cst[2 * JT];
    if (t < NI) {
        #pragma unroll
        for (int jj = 0; jj < JT; jj++) {
            float l1, h1, l2, h2;
            f2_unpack(s1p[jj], l1, h1);
            f2_unpack(s2p[jj], l2, h2);
            float mu  = (l1 + h1) * (1.f / DD);
            float var = fmaf(-mu, mu, (l2 + h2) * (1.f / DD));
            float rr  = rsqrtf(var + EPS);
            int j = jbase + jj;
            float s = q1 + kk1[j]; s = s > 0.f ? s : SLOPE * s;
            float a1 = __expf(s) * iZ1;
            float c1 = a1 * rr;
            s = q2 + kk2[j]; s = s > 0.f ? s : SLOPE * s;
            float a2 = __expf(s) * iZ2;
            float c2 = a2 * rr;
            cst[jj * 2 + 0] = c1; cst[jj * 2 + 1] = c2;
            ra[jj] = a1; rb[jj] = a2;
        }
        float* crow = c12 + t * 4;
        #pragma unroll
        for (int k = 0; k < 4; k++)
            *(float4*)(crow + k * 800) = make_float4(cst[k*4], cst[k*4+1], cst[k*4+2], cst[k*4+3]);
    } else {
        #pragma unroll
        for (int jj = 0; jj < JT; jj++) { ra[jj] = 0; rb[jj] = 0; }
    }

    // S0 reduction (half the old tree)
    #pragma unroll
    for (int jj = 0; jj < JT; jj++) {
        float v0 = ra[jj], v1 = rb[jj];
        #pragma unroll
        for (int o = 16; o > 0; o >>= 1) {
            v0 += __shfl_xor_sync(0xffffffffu, v0, o);
            v1 += __shfl_xor_sync(0xffffffffu, v1, o);
        }
        if (lane == 0) {
            red[warp * 16 + jj * 2 + 0] = v0;
            red[warp * 16 + jj * 2 + 1] = v1;
        }
    }
    __syncthreads();
    if (t < 16) {
        float s = 0.f;
        #pragma unroll
        for (int w = 0; w < 8; w++) s += red[w * 16 + t];
        Sc[t] = s;
    }
    __syncthreads();

    // ---- phase 2: warp (wj, ihalf): j-pair 2wj,2wj+1 over half the i range ----
    int wj    = warp & 3;
    int ihalf = warp >> 2;
    u64 a00 = 0, a01 = 0, a10 = 0, a11 = 0;
    {
        int i0 = ihalf * 100;
        const float* up = ua_s + 2 * lane;
        const float* cp = c12 + wj * 800;
        #pragma unroll 4
        for (int i = i0; i < i0 + 100; i++) {
            float2 u = *(const float2*)(up + i * 68);
            ulonglong2 cq = *(const ulonglong2*)(cp + i * 4);  // broadcast 16B
            u64 ux = f2_pack(u.x, u.x);
            u64 uy = f2_pack(u.y, u.y);
            a00 = f2_fma(cq.x, ux, a00);
            a01 = f2_fma(cq.x, uy, a01);
            a10 = f2_fma(cq.y, ux, a10);
            a11 = f2_fma(cq.y, uy, a11);
        }
    }
    __syncthreads();
    u64* pbuf = (u64*)c12;
    if (ihalf == 1) {
        u64* p = pbuf + ((size_t)(wj * 32 + lane)) * 4;
        p[0] = a00; p[1] = a01; p[2] = a10; p[3] = a11;
    }
    __syncthreads();
    if (ihalf == 0) {
        const u64* p = pbuf + ((size_t)(wj * 32 + lane)) * 4;
        a00 = f2_add(a00, p[0]);
        a01 = f2_add(a01, p[1]);
        a10 = f2_add(a10, p[2]);
        a11 = f2_add(a11, p[3]);
        float2 wl = *(const float2*)(wln + 2 * lane);
        float2 bl = *(const float2*)(bln + 2 * lane);
        #pragma unroll
        for (int k = 0; k < 2; k++) {
            int jj = 2 * wj + k;
            u64 S1x = k ? a10 : a00;
            u64 S1y = k ? a11 : a01;
            int j = jbase + jj;
            float2 uj = *(const float2*)(ua_s + j * 68 + 2 * lane);
            u64 ujx = f2_pack(uj.x, uj.x);
            u64 ujy = f2_pack(uj.y, uj.y);

            // S2 = <ua_j, S1[j,:]> / 64  (heads packed), warp all-reduce
            u64 pr = f2_fma(ujy, S1y, f2_mul(ujx, S1x));
            float pa, pb;
            f2_unpack(pr, pa, pb);
            #pragma unroll
            for (int o = 16; o > 0; o >>= 1) {
                pa += __shfl_xor_sync(0xffffffffu, pa, o);
                pb += __shfl_xor_sync(0xffffffffu, pb, o);
            }
            float S2a = pa * (1.f / DD), S2b = pb * (1.f / DD);

            u64 S0  = f2_pack(Sc[jj * 2 + 0], Sc[jj * 2 + 1]);
            u64 S2n = f2_pack(-S2a, -S2b);
            u64 X  = f2_fma(ujx, S1x, S2n);
            u64 at = f2_fma(f2_pack(bl.x, bl.x), S0, f2_mul(f2_pack(wl.x, wl.x), X));
            float t1, t2;
            f2_unpack(at, t1, t2);
            float ox = 0.5f * (t1 + t2);
            X  = f2_fma(ujy, S1y, S2n);
            at = f2_fma(f2_pack(bl.y, bl.y), S0, f2_mul(f2_pack(wl.y, wl.y), X));
            f2_unpack(at, t1, t2);
            float oy = 0.5f * (t1 + t2);
            ox = ox > 0.f ? ox : SLOPE * ox;
            oy = oy > 0.f ? oy : SLOPE * oy;
            *(float2*)(out + (size_t)(b * 201 + 1 + j) * DD + 2 * lane) = make_float2(ox, oy);
        }
    }
}

// ---------------- launch ----------------
extern "C" void kernel_launch(void* const* d_in, const int* in_sizes, int n_in,
                              void* d_out, int out_size) {
    const float* emb = (const float*)d_in[0];
    const float* lnw = (const float*)d_in[1];
    const float* lnb = (const float*)d_in[2];
    const float* W1  = (const float*)d_in[3];
    const float* W1b = (const float*)d_in[4];
    const float* W2  = (const float*)d_in[5];
    const float* W2b = (const float*)d_in[6];
    const float* a1  = (const float*)d_in[7];
    const float* a1b = (const float*)d_in[8];
    const float* a2  = (const float*)d_in[9];
    const float* a2b = (const float*)d_in[10];
    float* out = (float*)d_out;
    (void)in_sizes; (void)n_in; (void)out_size;

    cudaFuncSetAttribute(kA_prep, cudaFuncAttributeMaxDynamicSharedMemorySize, A_BYTES);
    cudaFuncSetAttribute(k3_main, cudaFuncAttributeMaxDynamicSharedMemorySize, SMEM_BYTES);

    dim3 gA(4, BN);
    kA_prep<<<gA, 256, A_BYTES>>>(emb, lnw, lnb, W1, W1b, W2, W2b,
                                  a1, a1b, a2, a2b, out);
    dim3 g3(NTILES, BN);
    k3_main<<<g3, 256, SMEM_BYTES>>>(lnw, lnb, out);
}

// round 8
// speedup vs baseline: 1.2947x; 1.0007x over previous
#include <cuda_runtime.h>
#include <math.h>

#define BN    32
#define NODES 202
#define NI    200
#define DD    64
#define JT    8
#define NTILES (NI/JT)   // 25
#define EPS   1e-5f
#define SLOPE 0.01f

typedef unsigned long long u64;

// ---- packed fp32x2 helpers (sm_103a) ----
__device__ __forceinline__ u64 f2_mul(u64 a, u64 b) {
    u64 r; asm("mul.rn.f32x2 %0,%1,%2;" : "=l"(r) : "l"(a), "l"(b)); return r;
}
__device__ __forceinline__ u64 f2_add(u64 a, u64 b) {
    u64 r; asm("add.rn.f32x2 %0,%1,%2;" : "=l"(r) : "l"(a), "l"(b)); return r;
}
__device__ __forceinline__ u64 f2_fma(u64 a, u64 b, u64 c) {
    u64 r; asm("fma.rn.f32x2 %0,%1,%2,%3;" : "=l"(r) : "l"(a), "l"(b), "l"(c)); return r;
}
__device__ __forceinline__ u64 f2_pack(float lo, float hi) {
    u64 r; asm("mov.b64 %0,{%1,%2};" : "=l"(r) : "f"(lo), "f"(hi)); return r;
}
__device__ __forceinline__ void f2_unpack(u64 v, float& lo, float& hi) {
    asm("mov.b64 {%0,%1},%2;" : "=f"(lo), "=f"(hi) : "l"(v));
}

// ---------------- device scratch ----------------
__device__ float g_ua[BN * NI * DD];
__device__ float g_qk[BN * 4 * NI];      // [b][0:q1 1:k1 2:q2 3:k2][i]
__device__ float g_prm[BN * NI * 8];     // (q1,k1,iZ1,q2),(k2,iZ2,_,_)

// =======================================================================
// kA1: per-batch-half prep. grid (2, BN), 256 threads.
// Stages ONLY its own 102 raw rows; computes ua + q/k for its 100 i's.
#define B_W    0        // 8192  W_s[h*4096+o*64+d]
#define B_A    8192     // 384
#define B_WB   8576     // 128
#define B_LNW  8704     // 64
#define B_LNB  8768     // 64
#define B_RAW  8832     // 102*68 = 6936
#define B_UA   15768    // 100*68 = 6800
#define B_MU   22568    // 102
#define B_RS   22670    // 102
#define B_UID  22772    // 64
#define B_IID  22836    // 64
#define B_VQ   22900    // 128
#define B_VK   23028    // 128
#define B_RED  23156    // 8
#define B_CQK  23164    // 6
#define B_QC   23170    // 2
#define B_KC   23172    // 2
#define B_FLOATS 23174
#define B_BYTES  (B_FLOATS * 4)

extern __shared__ float smB[];

__global__ __launch_bounds__(256, 1)
void kA1_prep(const float* __restrict__ emb,
              const float* __restrict__ lnw, const float* __restrict__ lnb,
              const float* __restrict__ W1, const float* __restrict__ W1b,
              const float* __restrict__ W2, const float* __restrict__ W2b,
              const float* __restrict__ a1, const float* __restrict__ a1b,
              const float* __restrict__ a2, const float* __restrict__ a2b,
              float* __restrict__ out) {
    int h    = blockIdx.x;     // half 0/1
    int b    = blockIdx.y;
    int t    = threadIdx.x;
    int warp = t >> 5, lane = t & 31;

    float* W_s   = smB + B_W;
    float* a_s   = smB + B_A;
    float* wb_s  = smB + B_WB;
    float* lnw_s = smB + B_LNW;
    float* lnb_s = smB + B_LNB;
    float* raw   = smB + B_RAW;   // stride 68, 102 rows (rows 0,1 then own 100)
    float* ua_s  = smB + B_UA;    // stride 68, 100 rows
    float* mu_s  = smB + B_MU;
    float* rs_s  = smB + B_RS;
    float* uid   = smB + B_UID;
    float* iid   = smB + B_IID;
    float* vq_s  = smB + B_VQ;
    float* vk_s  = smB + B_VK;
    float* red   = smB + B_RED;
    float* cqk   = smB + B_CQK;
    float* qc_s  = smB + B_QC;
    float* kc_s  = smB + B_KC;

    // ---- P0: stage weights + own raw rows ----
    for (int idx = t; idx < 2048; idx += 256) {
        int hh = idx >> 10;
        ((float4*)W_s)[idx] = ((const float4*)(hh ? W2 : W1))[idx & 1023];
    }
    for (int idx = t; idx < 384; idx += 256)
        a_s[idx] = (idx < 192) ? a1[idx] : a2[idx - 192];
    if (t < 128) wb_s[t] = (t < 64) ? W1b[t] : W2b[t - 64];
    if (t < 64) { lnw_s[t] = lnw[t]; lnb_s[t] = lnb[t]; }
    const float4* e4 = (const float4*)(emb + (size_t)b * NODES * DD);
    for (int idx = t; idx < 102 * 16; idx += 256) {
        int r = idx >> 4, c = idx & 15;
        int g = (r < 2) ? r : r + 100 * h;
        *(float4*)(raw + r * 68 + c * 4) = e4[g * 16 + c];
    }
    __syncthreads();

    // ---- P1: row stats (102 rows) + bias dots ----
    if (t < 102) {
        const float* rp = raw + t * 68;
        float s = 0.f, ss = 0.f;
        #pragma unroll
        for (int c = 0; c < 16; c++) {
            float4 v = *(const float4*)(rp + c * 4);
            s += (v.x + v.y) + (v.z + v.w);
            ss = fmaf(v.x, v.x, fmaf(v.y, v.y, fmaf(v.z, v.z, fmaf(v.w, v.w, ss))));
        }
        float m = s * (1.f / DD);
        float var = fmaf(-m, m, ss * (1.f / DD));
        mu_s[t] = m;
        rs_s[t] = rsqrtf(var + EPS);
    }
    if (t >= 208 && t < 214) {
        int idx = t - 208, hh = idx / 3, wch = idx % 3;
        float s = 0.f;
        #pragma unroll 8
        for (int o = 0; o < DD; o++)
            s = fmaf(a_s[hh * 192 + wch * 64 + o], wb_s[hh * 64 + o], s);
        cqk[idx] = s;
    }
    __syncthreads();

    // ---- P2: uid / iid ----
    if (t < 128) {
        int rw = t >> 6, d = t & 63;
        float v = fmaf((raw[rw * 68 + d] - mu_s[rw]) * rs_s[rw], lnw_s[d], lnb_s[d]);
        (rw ? iid : uid)[d] = v;
    }
    __syncthreads();
    if (h == 0 && t < DD) {
        float u = uid[t] * iid[t];
        out[(size_t)(b * 201) * DD + t] = u > 0.f ? u : SLOPE * u;
    }

    // ---- P3: ua for own 100 rows ----
    for (int idx = t; idx < 100 * 16; idx += 256) {
        int r = idx >> 4, c = idx & 15;
        float4 v = *(const float4*)(raw + (r + 2) * 68 + c * 4);
        float m = mu_s[r + 2], sc = rs_s[r + 2];
        float4 w4 = *(const float4*)(lnw_s + c * 4);
        float4 b4 = *(const float4*)(lnb_s + c * 4);
        float4 u4 = *(const float4*)(uid + c * 4);
        float4 o4;
        o4.x = fmaf((v.x - m) * sc, w4.x, b4.x) * u4.x;
        o4.y = fmaf((v.y - m) * sc, w4.y, b4.y) * u4.y;
        o4.z = fmaf((v.z - m) * sc, w4.z, b4.z) * u4.z;
        o4.w = fmaf((v.w - m) * sc, w4.w, b4.w) * u4.w;
        *(float4*)(ua_s + r * 68 + c * 4) = o4;
        ((float4*)(g_ua + ((size_t)b * NI + 100 * h + r) * DD))[c] = o4;
    }
    __syncthreads();

    // ---- P4: fold vq/vk + vi.iid ----
    if (t < 128) {
        int hh = t >> 6, d = t & 63;
        const float* Wp = W_s + hh * 4096 + d;
        const float* ap = a_s + hh * 192;
        float sqv = 0.f, skv = 0.f, siv = 0.f;
        #pragma unroll 8
        for (int o = 0; o < DD; o++) {
            float wv = Wp[o * 64];
            sqv = fmaf(ap[o],       wv, sqv);
            skv = fmaf(ap[64 + o],  wv, skv);
            siv = fmaf(ap[128 + o], wv, siv);
        }
        vq_s[hh * 64 + d] = sqv;
        vk_s[hh * 64 + d] = skv;
        float viid = siv * iid[d];
        #pragma unroll
        for (int o = 16; o > 0; o >>= 1) viid += __shfl_xor_sync(0xffffffffu, viid, o);
        if (lane == 0) red[warp] = viid;
    }
    __syncthreads();
    if (t == 0) {
        qc_s[0] = red[0] + red[1] + cqk[0] + cqk[2] + a1b[0];
        kc_s[0] = cqk[1];
        qc_s[1] = red[2] + red[3] + cqk[3] + cqk[5] + a2b[0];
        kc_s[1] = cqk[4];
    }
    __syncthreads();

    // ---- P5: q/k dots for own 100 i ----
    if (t < 100) {
        const float* u = ua_s + t * 68;
        float s10 = 0, s20 = 0, s11 = 0, s21 = 0;
        #pragma unroll
        for (int c = 0; c < 16; c++) {
            float4 uv = *(const float4*)(u + c * 4);
            float4 q0 = *(const float4*)(vq_s + c * 4);
            float4 k0 = *(const float4*)(vk_s + c * 4);
            float4 q1v = *(const float4*)(vq_s + 64 + c * 4);
            float4 k1v = *(const float4*)(vk_s + 64 + c * 4);
            s10 = fmaf(uv.x, q0.x, fmaf(uv.y, q0.y, fmaf(uv.z, q0.z, fmaf(uv.w, q0.w, s10))));
            s20 = fmaf(uv.x, k0.x, fmaf(uv.y, k0.y, fmaf(uv.z, k0.z, fmaf(uv.w, k0.w, s20))));
            s11 = fmaf(uv.x, q1v.x, fmaf(uv.y, q1v.y, fmaf(uv.z, q1v.z, fmaf(uv.w, q1v.w, s11))));
            s21 = fmaf(uv.x, k1v.x, fmaf(uv.y, k1v.y, fmaf(uv.z, k1v.z, fmaf(uv.w, k1v.w, s21))));
        }
        int i = 100 * h + t;
        float* gq = g_qk + (size_t)b * 800;
        gq[i]       = s10 + qc_s[0];
        gq[200 + i] = s20 + kc_s[0];
        gq[400 + i] = s11 + qc_s[1];
        gq[600 + i] = s21 + kc_s[1];
    }
}

// =======================================================================
// kA2: softmax Z. grid (4, BN), 256 threads, tiny smem.
__global__ __launch_bounds__(256, 8)
void kA2_z() {
    __shared__ float s_qk[800];
    __shared__ float zp[400];
    int q = blockIdx.x;     // quarter 0..3
    int b = blockIdx.y;
    int t = threadIdx.x;

    const float* gq = g_qk + (size_t)b * 800;
    for (int idx = t; idx < 800; idx += 256) s_qk[idx] = gq[idx];
    __syncthreads();

    if (t < 200) {
        int seg = t / 50, il = t % 50;
        int i = q * 50 + il;
        float q1 = s_qk[i], q2 = s_qk[400 + i];
        float Z1 = 0.f, Z2 = 0.f;
        int j0 = seg * 50;
        #pragma unroll 5
        for (int jj = 0; jj < 50; jj++) {
            int j = j0 + jj;
            float s = q1 + s_qk[200 + j]; s = s > 0.f ? s : SLOPE * s; Z1 += __expf(s);
            float r = q2 + s_qk[600 + j]; r = r > 0.f ? r : SLOPE * r; Z2 += __expf(r);
        }
        zp[seg * 50 + il]       = Z1;
        zp[200 + seg * 50 + il] = Z2;
    }
    __syncthreads();
    if (t < 50) {
        int i = q * 50 + t;
        float Z1 = zp[t] + zp[50 + t] + zp[100 + t] + zp[150 + t];
        float Z2 = zp[200 + t] + zp[250 + t] + zp[300 + t] + zp[350 + t];
        float4* p = (float4*)(g_prm + (size_t)(b * NI + i) * 8);
        p[0] = make_float4(s_qk[i], s_qk[200 + i], 1.f / Z1, s_qk[400 + i]);
        p[1] = make_float4(s_qk[600 + i], 1.f / Z2, 0.f, 0.f);
    }
}

// =======================================================================
// K3: main fused pair kernel (unchanged from R7)
#define OFF_UA   0
#define OFF_KK1  13600
#define OFF_KK2  13800
#define OFF_C12  14000     // 4*800 = 3200
#define OFF_WLN  17200
#define OFF_BLN  17264
#define OFF_SC   17328     // 16 (S0 only)
#define OFF_RED  17360     // 128
#define SMEM_FLOATS (OFF_RED + 128)   // 17488
#define SMEM_BYTES  (SMEM_FLOATS * 4)

extern __shared__ float sm3[];

__global__ __launch_bounds__(256, 3)
void k3_main(const float* __restrict__ lnw, const float* __restrict__ lnb,
             float* __restrict__ out) {
    int jt = blockIdx.x;
    int b  = blockIdx.y;
    int t  = threadIdx.x;
    int warp = t >> 5, lane = t & 31;

    float* ua_s = sm3 + OFF_UA;     // stride 68
    float* kk1  = sm3 + OFF_KK1;
    float* kk2  = sm3 + OFF_KK2;
    float* c12  = sm3 + OFF_C12;    // planes of 800
    float* wln  = sm3 + OFF_WLN;
    float* bln  = sm3 + OFF_BLN;
    float* Sc   = sm3 + OFF_SC;
    float* red  = sm3 + OFF_RED;

    const float4* uab4 = (const float4*)(g_ua + (size_t)b * NI * DD);
    for (int idx = t; idx < NI * 16; idx += 256) {
        int i = idx >> 4, c = idx & 15;
        *(float4*)(ua_s + i * 68 + c * 4) = uab4[idx];
    }
    if (t < 64) { wln[t] = lnw[t]; bln[t] = lnb[t]; }

    float q1 = 0, iZ1 = 0, q2 = 0, iZ2 = 0;
    if (t < NI) {
        const float4* pp = (const float4*)(g_prm + (size_t)(b * NI + t) * 8);
        float4 p0 = pp[0], p1 = pp[1];
        q1 = p0.x; kk1[t] = p0.y; iZ1 = p0.z; q2 = p0.w;
        kk2[t] = p1.x; iZ2 = p1.y;
    }
    __syncthreads();

    int jbase = jt * JT;

    // ---- phase 1: Gram stats (packed f32x2, j-register-tiled) ----
    u64 s1p[JT], s2p[JT];
    #pragma unroll
    for (int jj = 0; jj < JT; jj++) { s1p[jj] = 0ull; s2p[jj] = 0ull; }

    if (t < NI) {
        const float* ui = ua_s + t * 68;
        const float* ujb = ua_s + jbase * 68;
        #pragma unroll 4
        for (int dc = 0; dc < 16; dc++) {
            ulonglong2 u = *(const ulonglong2*)(ui + dc * 4);
            #pragma unroll
            for (int jj = 0; jj < JT; jj++) {
                ulonglong2 v = *(const ulonglong2*)(ujb + jj * 68 + dc * 4);  // broadcast
                u64 p0 = f2_mul(u.x, v.x);
                u64 p1 = f2_mul(u.y, v.y);
                s1p[jj] = f2_add(s1p[jj], p0);
                s1p[jj] = f2_add(s1p[jj], p1);
                s2p[jj] = f2_fma(p0, p0, s2p[jj]);
                s2p[jj] = f2_fma(p1, p1, s2p[jj]);
            }
        }
    }

    float ra[JT], rb[JT];
    float cst[2 * JT];
    if (t < NI) {
        #pragma unroll
        for (int jj = 0; jj < JT; jj++) {
            float l1, h1, l2, h2;
            f2_unpack(s1p[jj], l1, h1);
            f2_unpack(s2p[jj], l2, h2);
            float mu  = (l1 + h1) * (1.f / DD);
            float var = fmaf(-mu, mu, (l2 + h2) * (1.f / DD));
            float rr  = rsqrtf(var + EPS);
            int j = jbase + jj;
            float s = q1 + kk1[j]; s = s > 0.f ? s : SLOPE * s;
            float a1 = __expf(s) * iZ1;
            float c1 = a1 * rr;
            s = q2 + kk2[j]; s = s > 0.f ? s : SLOPE * s;
            float a2 = __expf(s) * iZ2;
            float c2 = a2 * rr;
            cst[jj * 2 + 0] = c1; cst[jj * 2 + 1] = c2;
            ra[jj] = a1; rb[jj] = a2;
        }
        float* crow = c12 + t * 4;
        #pragma unroll
        for (int k = 0; k < 4; k++)
            *(float4*)(crow + k * 800) = make_float4(cst[k*4], cst[k*4+1], cst[k*4+2], cst[k*4+3]);
    } else {
        #pragma unroll
        for (int jj = 0; jj < JT; jj++) { ra[jj] = 0; rb[jj] = 0; }
    }

    #pragma unroll
    for (int jj = 0; jj < JT; jj++) {
        float v0 = ra[jj], v1 = rb[jj];
        #pragma unroll
        for (int o = 16; o > 0; o >>= 1) {
            v0 += __shfl_xor_sync(0xffffffffu, v0, o);
            v1 += __shfl_xor_sync(0xffffffffu, v1, o);
        }
        if (lane == 0) {
            red[warp * 16 + jj * 2 + 0] = v0;
            red[warp * 16 + jj * 2 + 1] = v1;
        }
    }
    __syncthreads();
    if (t < 16) {
        float s = 0.f;
        #pragma unroll
        for (int w = 0; w < 8; w++) s += red[w * 16 + t];
        Sc[t] = s;
    }
    __syncthreads();

    // ---- phase 2 ----
    int wj    = warp & 3;
    int ihalf = warp >> 2;
    u64 a00 = 0, a01 = 0, a10 = 0, a11 = 0;
    {
        int i0 = ihalf * 100;
        const float* up = ua_s + 2 * lane;
        const float* cp = c12 + wj * 800;
        #pragma unroll 4
        for (int i = i0; i < i0 + 100; i++) {
            float2 u = *(const float2*)(up + i * 68);
            ulonglong2 cq = *(const ulonglong2*)(cp + i * 4);  // broadcast 16B
            u64 ux = f2_pack(u.x, u.x);
            u64 uy = f2_pack(u.y, u.y);
            a00 = f2_fma(cq.x, ux, a00);
            a01 = f2_fma(cq.x, uy, a01);
            a10 = f2_fma(cq.y, ux, a10);
            a11 = f2_fma(cq.y, uy, a11);
        }
    }
    __syncthreads();
    u64* pbuf = (u64*)c12;
    if (ihalf == 1) {
        u64* p = pbuf + ((size_t)(wj * 32 + lane)) * 4;
        p[0] = a00; p[1] = a01; p[2] = a10; p[3] = a11;
    }
    __syncthreads();
    if (ihalf == 0) {
        const u64* p = pbuf + ((size_t)(wj * 32 + lane)) * 4;
        a00 = f2_add(a00, p[0]);
        a01 = f2_add(a01, p[1]);
        a10 = f2_add(a10, p[2]);
        a11 = f2_add(a11, p[3]);
        float2 wl = *(const float2*)(wln + 2 * lane);
        float2 bl = *(const float2*)(bln + 2 * lane);
        #pragma unroll
        for (int k = 0; k < 2; k++) {
            int jj = 2 * wj + k;
            u64 S1x = k ? a10 : a00;
            u64 S1y = k ? a11 : a01;
            int j = jbase + jj;
            float2 uj = *(const float2*)(ua_s + j * 68 + 2 * lane);
            u64 ujx = f2_pack(uj.x, uj.x);
            u64 ujy = f2_pack(uj.y, uj.y);

            u64 pr = f2_fma(ujy, S1y, f2_mul(ujx, S1x));
            float pa, pb;
            f2_unpack(pr, pa, pb);
            #pragma unroll
            for (int o = 16; o > 0; o >>= 1) {
                pa += __shfl_xor_sync(0xffffffffu, pa, o);
                pb += __shfl_xor_sync(0xffffffffu, pb, o);
            }
            float S2a = pa * (1.f / DD), S2b = pb * (1.f / DD);

            u64 S0  = f2_pack(Sc[jj * 2 + 0], Sc[jj * 2 + 1]);
            u64 S2n = f2_pack(-S2a, -S2b);
            u64 X  = f2_fma(ujx, S1x, S2n);
            u64 at = f2_fma(f2_pack(bl.x, bl.x), S0, f2_mul(f2_pack(wl.x, wl.x), X));
            float t1, t2;
            f2_unpack(at, t1, t2);
            float ox = 0.5f * (t1 + t2);
            X  = f2_fma(ujy, S1y, S2n);
            at = f2_fma(f2_pack(bl.y, bl.y), S0, f2_mul(f2_pack(wl.y, wl.y), X));
            f2_unpack(at, t1, t2);
            float oy = 0.5f * (t1 + t2);
            ox = ox > 0.f ? ox : SLOPE * ox;
            oy = oy > 0.f ? oy : SLOPE * oy;
            *(float2*)(out + (size_t)(b * 201 + 1 + j) * DD + 2 * lane) = make_float2(ox, oy);
        }
    }
}

// ---------------- launch ----------------
extern "C" void kernel_launch(void* const* d_in, const int* in_sizes, int n_in,
                              void* d_out, int out_size) {
    const float* emb = (const float*)d_in[0];
    const float* lnw = (const float*)d_in[1];
    const float* lnb = (const float*)d_in[2];
    const float* W1  = (const float*)d_in[3];
    const float* W1b = (const float*)d_in[4];
    const float* W2  = (const float*)d_in[5];
    const float* W2b = (const float*)d_in[6];
    const float* a1  = (const float*)d_in[7];
    const float* a1b = (const float*)d_in[8];
    const float* a2  = (const float*)d_in[9];
    const float* a2b = (const float*)d_in[10];
    float* out = (float*)d_out;
    (void)in_sizes; (void)n_in; (void)out_size;

    cudaFuncSetAttribute(kA1_prep, cudaFuncAttributeMaxDynamicSharedMemorySize, B_BYTES);
    cudaFuncSetAttribute(k3_main, cudaFuncAttributeMaxDynamicSharedMemorySize, SMEM_BYTES);

    dim3 gA1(2, BN);
    kA1_prep<<<gA1, 256, B_BYTES>>>(emb, lnw, lnb, W1, W1b, W2, W2b,
                                    a1, a1b, a2, a2b, out);
    dim3 gA2(4, BN);
    kA2_z<<<gA2, 256>>>();
    dim3 g3(NTILES, BN);
    k3_main<<<g3, 256, SMEM_BYTES>>>(lnw, lnb, out);
}